// round 9
// baseline (speedup 1.0000x reference)
#include <cuda_runtime.h>
#include <cuda_bf16.h>
#include <cstdint>

// Problem constants
#define BATCH 8192
#define FEAT  512
#define DEG   32
#define F2    1024   // 2*FEAT
#define F3    1536   // 3*FEAT
#define BN_EPS 1e-5f

// Output layout (floats): agg, to_feats, gen, raw, env_gen, env_raw
#define OFF_AGG   0
#define OFF_TO    (BATCH*FEAT)
#define OFF_GEN   (OFF_TO   + BATCH*F3)
#define OFF_RAW   (OFF_GEN  + BATCH*F2)
#define OFF_EGEN  (OFF_RAW  + BATCH*F2)
#define OFF_ERAW  (OFF_EGEN + BATCH*F2)

// ---------------- scratch (__device__ globals; no allocations) --------------
__device__ float g_cat [(size_t)BATCH * F2];   // [self | agg] tf32-rounded
__device__ float g_env [(size_t)BATCH * FEAT]; // env_agg tf32-rounded
__device__ float g_genr[(size_t)BATCH * F2];   // tf32-rounded relu(raw) = gen
__device__ float g_WgT [(size_t)F2 * F2];      // W_gen^T rounded, [N][K] K-major
__device__ float g_W1sT[(size_t)F3 * F3];      // round(s_k*W1[k][n])^T, [N][K]
__device__ float g_s[F3];
__device__ float g_t[F3];
__device__ float g_bias[F3];                   // t @ W1
__device__ float g_bnsum[F3];
__device__ float g_bnsq[F3];

// ------------------------------- helpers ------------------------------------
__device__ __forceinline__ float tf32r(float v) {
    uint32_t u;
    asm("cvt.rna.tf32.f32 %0, %1;" : "=r"(u) : "f"(v));
    return __uint_as_float(u);
}
__device__ __forceinline__ float4 tf32r4(float4 v) {
    return make_float4(tf32r(v.x), tf32r(v.y), tf32r(v.z), tf32r(v.w));
}
__device__ __forceinline__ uint32_t smem_u32(const void* p) {
    uint32_t a;
    asm("{ .reg .u64 t; cvta.to.shared.u64 t, %1; cvt.u32.u64 %0, t; }"
        : "=r"(a) : "l"(p));
    return a;
}
__device__ __forceinline__ void cp_async16(uint32_t dst, const void* src) {
    asm volatile("cp.async.cg.shared.global [%0], [%1], 16;" :: "r"(dst), "l"(src));
}
#define CP_COMMIT() asm volatile("cp.async.commit_group;" ::: "memory")
#define CP_WAIT(n)  asm volatile("cp.async.wait_group %0;" :: "n"(n) : "memory")

__device__ __forceinline__ void ldsm4(uint32_t& r0, uint32_t& r1, uint32_t& r2,
                                      uint32_t& r3, uint32_t addr) {
    asm volatile("ldmatrix.sync.aligned.m8n8.x4.shared.b16 {%0,%1,%2,%3}, [%4];"
                 : "=r"(r0), "=r"(r1), "=r"(r2), "=r"(r3) : "r"(addr));
}
__device__ __forceinline__ void mma_tf32(float* c, const uint32_t* a, const uint32_t* b) {
    asm volatile(
        "mma.sync.aligned.m16n8k8.row.col.f32.tf32.tf32.f32 "
        "{%0,%1,%2,%3}, {%4,%5,%6,%7}, {%8,%9}, {%0,%1,%2,%3};"
        : "+f"(c[0]), "+f"(c[1]), "+f"(c[2]), "+f"(c[3])
        : "r"(a[0]), "r"(a[1]), "r"(a[2]), "r"(a[3]), "r"(b[0]), "r"(b[1]));
}

// ---------------------------------------------------------------------------
// Gather + mean-pool (also writes tf32-rounded staging for GEMMs).
// ---------------------------------------------------------------------------
__global__ void gather_kernel(const float* __restrict__ feat,
                              const int*  __restrict__ neigh,
                              float* __restrict__ aggO)
{
    const int m = blockIdx.x;
    __shared__ int idx[DEG];
    if (threadIdx.x < DEG) idx[threadIdx.x] = neigh[(size_t)m * DEG + threadIdx.x];
    __syncthreads();

    const int c = threadIdx.x * 4;

    float4 v0 = *(const float4*)(feat + (size_t)idx[0] * FEAT + c);
    float sx = v0.x, sy = v0.y, sz = v0.z, sw = v0.w;
#pragma unroll 8
    for (int j = 1; j < DEG; j++) {
        float4 v = *(const float4*)(feat + (size_t)idx[j] * FEAT + c);
        sx += v.x; sy += v.y; sz += v.z; sw += v.w;
    }
    const float r32 = 1.0f / 32.0f;
    const float r31 = 1.0f / 31.0f;
    float4 agg = make_float4(sx * r32, sy * r32, sz * r32, sw * r32);
    float4 env = make_float4((sx - v0.x) * r31, (sy - v0.y) * r31,
                             (sz - v0.z) * r31, (sw - v0.w) * r31);

    *(float4*)(g_cat + (size_t)m * F2 + c)        = tf32r4(v0);
    *(float4*)(g_cat + (size_t)m * F2 + FEAT + c) = tf32r4(agg);
    *(float4*)(aggO  + (size_t)m * FEAT + c)      = agg;     // exact output
    *(float4*)(g_env + (size_t)m * FEAT + c)      = tf32r4(env);
}

// ---------------------------------------------------------------------------
// Transpose + tf32 round (+ optional per-source-row scale by g_s).
// ---------------------------------------------------------------------------
template <bool SCALE>
__global__ void transpose_round(const float* __restrict__ src,
                                float* __restrict__ dst, int R, int C)
{
    __shared__ float t[32][33];
    const int bx = blockIdx.x * 32, by = blockIdx.y * 32;
#pragma unroll
    for (int j = 0; j < 32; j += 8)
        t[threadIdx.y + j][threadIdx.x] =
            src[(size_t)(by + threadIdx.y + j) * C + bx + threadIdx.x];
    __syncthreads();
    const float sc = SCALE ? g_s[by + threadIdx.x] : 1.0f;
#pragma unroll
    for (int j = 0; j < 32; j += 8) {
        float v = t[threadIdx.x][threadIdx.y + j];
        if (SCALE) v *= sc;
        dst[(size_t)(bx + threadIdx.y + j) * R + by + threadIdx.x] = tf32r(v);
    }
}

// bias[n] = sum_k t[k] * W1[k][n].
__global__ void bias_kernel(const float* __restrict__ W1)
{
    const int n = blockIdx.x * 32 + (threadIdx.x & 31);
    const int kl = threadIdx.x >> 5;   // 0..7
    float sum = 0.f;
    for (int k = kl; k < F3; k += 8)
        sum += g_t[k] * W1[(size_t)k * F3 + n];
    __shared__ float red[8][32];
    red[kl][threadIdx.x & 31] = sum;
    __syncthreads();
    if (kl == 0) {
#pragma unroll
        for (int r = 1; r < 8; r++) sum += red[r][threadIdx.x & 31];
        g_bias[n] = sum;
    }
}

// ---------------------------------------------------------------------------
// tf32 mma.sync GEMM, 2 CTAs/SM. Block 128x128x32, 8 warps (2x4), warp 64x32.
// 3-stage cp.async ring. ldmatrix operand loads. Ops as in round 7/8.
// SMEM per stage: As[128][36] + Bs[128][36] rows of 144 B.
// ---------------------------------------------------------------------------
#define BM 128
#define BN 128
#define BK 32
#define NSTAGE 3
#define OP_STRIDE 144
#define A_BYTES (BM * OP_STRIDE)                   // 18432
#define STAGE_BYTES (2 * A_BYTES)                  // 36864 (A + B)

struct GemmCore {
    uint32_t sbase;
    int tid, wid, lane, wm, wn, lr, lc;
    uint32_t aOff, bOff;

    __device__ __forceinline__ void init(uint32_t sb) {
        sbase = sb;
        tid = threadIdx.x; wid = tid >> 5; lane = tid & 31;
        wm = wid >> 2; wn = wid & 3;
        lr = lane >> 2; lc = lane & 3;
        const int a_row = wm * 64 + (lane & 15);
        const int a_col = (lane >> 4) * 4;
        aOff = (uint32_t)a_row * OP_STRIDE + a_col * 4;
        const int b_row = wn * 32 + (lane & 7) + (lane >> 4) * 8;
        const int b_col = ((lane >> 3) & 1) * 4;
        bOff = (uint32_t)b_row * OP_STRIDE + b_col * 4;
    }

    __device__ __forceinline__ void load_stage(const float* Ap, int lda,
                                               const float* Bp, int ldb, int s) {
        const uint32_t a_s = sbase + (uint32_t)s * STAGE_BYTES;
        const uint32_t b_s = a_s + A_BYTES;
#pragma unroll
        for (int u = 0; u < 4; u++) {
            int ch = tid + u * 256;
            int row = ch >> 3, c16 = ch & 7;
            cp_async16(a_s + (uint32_t)row * OP_STRIDE + c16 * 16,
                       Ap + (size_t)row * lda + c16 * 4);
        }
#pragma unroll
        for (int u = 0; u < 4; u++) {
            int ch = tid + u * 256;
            int row = ch >> 3, c16 = ch & 7;
            cp_async16(b_s + (uint32_t)row * OP_STRIDE + c16 * 16,
                       Bp + (size_t)row * ldb + c16 * 4);
        }
    }

    __device__ __forceinline__ void compute_stage(int s, float acc[4][4][4]) {
        const uint32_t a_s0 = sbase + (uint32_t)s * STAGE_BYTES;
#pragma unroll
        for (int k8 = 0; k8 < BK / 8; k8++) {
            const uint32_t a_s = a_s0 + (uint32_t)k8 * 32;
            const uint32_t b_s = a_s + A_BYTES;
            uint32_t a[4][4], b[2][4];
#pragma unroll
            for (int mi = 0; mi < 4; mi++)
                ldsm4(a[mi][0], a[mi][1], a[mi][2], a[mi][3],
                      a_s + aOff + (uint32_t)mi * (16 * OP_STRIDE));
#pragma unroll
            for (int nb = 0; nb < 2; nb++)
                ldsm4(b[nb][0], b[nb][1], b[nb][2], b[nb][3],
                      b_s + bOff + (uint32_t)nb * (16 * OP_STRIDE));
#pragma unroll
            for (int mi = 0; mi < 4; mi++)
#pragma unroll
                for (int nb = 0; nb < 2; nb++) {
                    mma_tf32(acc[mi][2 * nb + 0], a[mi], &b[nb][0]);
                    mma_tf32(acc[mi][2 * nb + 1], a[mi], &b[nb][2]);
                }
        }
    }
};

// GEMM1 + GEMM2 merged via blockIdx.z.
// z=0: raw/gen/genr = cat @ WgT      (K=F2)
// z=1: eraw/egen    = env @ WgT+FEAT (K=FEAT)
__global__ void __launch_bounds__(256, 2)
mma_gemm12(const float* __restrict__ cat, const float* __restrict__ env,
           const float* __restrict__ WgT,
           float* __restrict__ raw, float* __restrict__ gen,
           float* __restrict__ genr,
           float* __restrict__ eraw, float* __restrict__ egen)
{
    extern __shared__ __align__(16) char smem[];
    GemmCore g; g.init(smem_u32(smem));
    const int m0 = blockIdx.y * BM, n0 = blockIdx.x * BN;

    const float* A; const float* Bp; int K;
    float *C0, *C1, *C2;
    if (blockIdx.z == 0) {
        A = cat + (size_t)m0 * F2; K = F2;
        Bp = WgT + (size_t)n0 * F2;
        C0 = raw; C1 = gen; C2 = genr;
    } else {
        A = env + (size_t)m0 * FEAT; K = FEAT;
        Bp = WgT + FEAT + (size_t)n0 * F2;
        C0 = eraw; C1 = egen; C2 = nullptr;
    }
    const int lda = (blockIdx.z == 0) ? F2 : FEAT;
    const int T = K / BK;

    float acc[4][4][4];
#pragma unroll
    for (int i = 0; i < 4; i++)
#pragma unroll
        for (int j = 0; j < 4; j++)
#pragma unroll
            for (int r = 0; r < 4; r++) acc[i][j][r] = 0.f;

    g.load_stage(A, lda, Bp, F2, 0); CP_COMMIT();
    g.load_stage(A + BK, lda, Bp + BK, F2, 1); CP_COMMIT();

    for (int i = 0; i < T; i++) {
        if (i + 2 < T) g.load_stage(A + (i + 2) * BK, lda, Bp + (i + 2) * BK, F2,
                                    (i + 2) % NSTAGE);
        CP_COMMIT();
        CP_WAIT(2);
        __syncthreads();
        g.compute_stage(i % NSTAGE, acc);
        __syncthreads();
    }

    // Epilogue
#pragma unroll
    for (int mi = 0; mi < 4; mi++) {
#pragma unroll
        for (int half = 0; half < 2; half++) {
            const size_t row = (size_t)m0 + g.wm * 64 + mi * 16 + g.lr + half * 8;
#pragma unroll
            for (int ni = 0; ni < 4; ni++) {
                const int col = n0 + g.wn * 32 + ni * 8 + g.lc * 2;
                float x = acc[mi][ni][half * 2 + 0];
                float y = acc[mi][ni][half * 2 + 1];
                *(float2*)(C0 + row * F2 + col) = make_float2(x, y);
                float rx = fmaxf(x, 0.f), ry = fmaxf(y, 0.f);
                *(float2*)(C1 + row * F2 + col) = make_float2(rx, ry);
                if (C2)
                    *(float2*)(C2 + row * F2 + col) = make_float2(tf32r(rx), tf32r(ry));
            }
        }
    }
}

// GEMM3: to = relu([aggR | genr] @ W1sT + bias), A split at k=FEAT.
__global__ void __launch_bounds__(256, 2)
mma_gemm3(const float* __restrict__ aggR, const float* __restrict__ genr,
          const float* __restrict__ W1sT, float* __restrict__ C0,
          const float* __restrict__ bias)
{
    extern __shared__ __align__(16) char smem[];
    GemmCore g; g.init(smem_u32(smem));
    const int m0 = blockIdx.y * BM, n0 = blockIdx.x * BN;
    const int T = F3 / BK;

    const float* Bp = W1sT + (size_t)n0 * F3;

    auto aptr = [&](int blk) -> const float* {
        int k0 = blk * BK;
        if (k0 < FEAT) return aggR + (size_t)m0 * F2 + k0;
        return genr + (size_t)m0 * F2 + (k0 - FEAT);
    };

    float acc[4][4][4];
#pragma unroll
    for (int i = 0; i < 4; i++)
#pragma unroll
        for (int j = 0; j < 4; j++)
#pragma unroll
            for (int r = 0; r < 4; r++) acc[i][j][r] = 0.f;

    g.load_stage(aptr(0), F2, Bp, F3, 0); CP_COMMIT();
    g.load_stage(aptr(1), F2, Bp + BK, F3, 1); CP_COMMIT();

    for (int i = 0; i < T; i++) {
        if (i + 2 < T) g.load_stage(aptr(i + 2), F2, Bp + (i + 2) * BK, F3,
                                    (i + 2) % NSTAGE);
        CP_COMMIT();
        CP_WAIT(2);
        __syncthreads();
        g.compute_stage(i % NSTAGE, acc);
        __syncthreads();
    }

#pragma unroll
    for (int mi = 0; mi < 4; mi++) {
#pragma unroll
        for (int half = 0; half < 2; half++) {
            const size_t row = (size_t)m0 + g.wm * 64 + mi * 16 + g.lr + half * 8;
#pragma unroll
            for (int ni = 0; ni < 4; ni++) {
                const int col = n0 + g.wn * 32 + ni * 8 + g.lc * 2;
                float x = fmaxf(acc[mi][ni][half * 2 + 0] + bias[col], 0.f);
                float y = fmaxf(acc[mi][ni][half * 2 + 1] + bias[col + 1], 0.f);
                *(float2*)(C0 + row * F3 + col) = make_float2(x, y);
            }
        }
    }
}

// ---------------------------------------------------------------------------
// BN stats + finalize.
// ---------------------------------------------------------------------------
__global__ void bn_stats_kernel(const float* __restrict__ agg,
                                const float* __restrict__ gen)
{
    const int c0 = blockIdx.x * 32;
    const int cx = threadIdx.x & 31;
    const int ry = threadIdx.x >> 5;
    const int c  = c0 + cx;

    const float* base;
    int stride;
    if (c0 < FEAT) { base = agg + c;          stride = FEAT; }
    else           { base = gen + (c - FEAT); stride = F2;   }

    const int r0 = blockIdx.y * 512;
    float sum = 0.f, sq = 0.f;
#pragma unroll 8
    for (int r = r0 + ry; r < r0 + 512; r += 8) {
        float v = base[(size_t)r * stride];
        sum += v; sq += v * v;
    }
    __shared__ float ssum[8][32], ssq[8][32];
    ssum[ry][cx] = sum; ssq[ry][cx] = sq;
    __syncthreads();
    if (ry == 0) {
#pragma unroll
        for (int r = 1; r < 8; r++) { sum += ssum[r][cx]; sq += ssq[r][cx]; }
        atomicAdd(&g_bnsum[c], sum);
        atomicAdd(&g_bnsq[c], sq);
    }
}

__global__ void bn_finalize(const float* __restrict__ gamma,
                            const float* __restrict__ beta)
{
    int c = blockIdx.x * blockDim.x + threadIdx.x;
    if (c >= F3) return;
    const float inv = 1.0f / (float)BATCH;
    float mean = g_bnsum[c] * inv;
    float var  = g_bnsq[c] * inv - mean * mean;
    float s = gamma[c] * rsqrtf(var + BN_EPS);
    g_s[c] = s;
    g_t[c] = beta[c] - mean * s;
}

// ---------------------------------------------------------------------------
extern "C" void kernel_launch(void* const* d_in, const int* in_sizes, int n_in,
                              void* d_out, int out_size)
{
    const float* feat  = (const float*)d_in[0];
    const float* Wg    = (const float*)d_in[1];
    const float* W1    = (const float*)d_in[2];
    const float* gamma = (const float*)d_in[3];
    const float* beta  = (const float*)d_in[4];
    const int*   neigh = (const int*)d_in[6];

    float* out   = (float*)d_out;
    float* aggO  = out + OFF_AGG;
    float* toO   = out + OFF_TO;
    float* genO  = out + OFF_GEN;
    float* rawO  = out + OFF_RAW;
    float* egenO = out + OFF_EGEN;
    float* erawO = out + OFF_ERAW;

    float *p_cat, *p_env, *p_genr, *p_WgT, *p_W1sT, *p_sum, *p_sq, *p_bias;
    cudaGetSymbolAddress((void**)&p_cat,  g_cat);
    cudaGetSymbolAddress((void**)&p_env,  g_env);
    cudaGetSymbolAddress((void**)&p_genr, g_genr);
    cudaGetSymbolAddress((void**)&p_WgT,  g_WgT);
    cudaGetSymbolAddress((void**)&p_W1sT, g_W1sT);
    cudaGetSymbolAddress((void**)&p_sum,  g_bnsum);
    cudaGetSymbolAddress((void**)&p_sq,   g_bnsq);
    cudaGetSymbolAddress((void**)&p_bias, g_bias);

    const int smem_bytes = NSTAGE * STAGE_BYTES;   // 110592
    cudaFuncSetAttribute(mma_gemm12, cudaFuncAttributeMaxDynamicSharedMemorySize, smem_bytes);
    cudaFuncSetAttribute(mma_gemm3,  cudaFuncAttributeMaxDynamicSharedMemorySize, smem_bytes);

    // 0) W_gen -> K-major rounded; BN accumulator reset
    transpose_round<false><<<dim3(F2/32, F2/32), dim3(32, 8)>>>(Wg, p_WgT, F2, F2);
    cudaMemsetAsync(p_sum, 0, F3 * sizeof(float));
    cudaMemsetAsync(p_sq,  0, F3 * sizeof(float));

    // 1) gather + pooling (+tf32-rounded staging)
    gather_kernel<<<BATCH, 128>>>(feat, neigh, aggO);

    // 2+3) GEMM1 (z=0) + GEMM2 (z=1) in one launch
    mma_gemm12<<<dim3(F2/BN, BATCH/BM, 2), 256, smem_bytes>>>(
        p_cat, p_env, p_WgT, rawO, genO, p_genr, erawO, egenO);

    // 4) BN statistics + finalize
    bn_stats_kernel<<<dim3(F3/32, 16), 256>>>(aggO, genO);
    bn_finalize<<<F3/256, 256>>>(gamma, beta);

    // 5) fold BN into GEMM3: W1sT[n][k] = round(s_k * W1[k][n]); bias = t @ W1
    transpose_round<true><<<dim3(F3/32, F3/32), dim3(32, 8)>>>(W1, p_W1sT, F3, F3);
    bias_kernel<<<F3/32, 256>>>(W1);

    // 6) to_feats = relu([agg|gen]_r @ (sW1) + bias)
    mma_gemm3<<<dim3(F3/BN, BATCH/BM), 256, smem_bytes>>>(
        p_cat + FEAT, p_genr, p_W1sT, toO, p_bias);

    (void)in_sizes; (void)n_in; (void)out_size;
}

// round 10
// speedup vs baseline: 1.3527x; 1.3527x over previous
#include <cuda_runtime.h>
#include <cuda_bf16.h>
#include <cstdint>

// Problem constants
#define BATCH 8192
#define FEAT  512
#define DEG   32
#define F2    1024   // 2*FEAT
#define F3    1536   // 3*FEAT
#define BN_EPS 1e-5f

// Output layout (floats): agg, to_feats, gen, raw, env_gen, env_raw
#define OFF_AGG   0
#define OFF_TO    (BATCH*FEAT)
#define OFF_GEN   (OFF_TO   + BATCH*F3)
#define OFF_RAW   (OFF_GEN  + BATCH*F2)
#define OFF_EGEN  (OFF_RAW  + BATCH*F2)
#define OFF_ERAW  (OFF_EGEN + BATCH*F2)

// ---------------- scratch (__device__ globals; no allocations) --------------
__device__ float g_cat [(size_t)BATCH * F2];   // [self | agg] tf32-rounded
__device__ float g_env [(size_t)BATCH * FEAT]; // env_agg tf32-rounded
__device__ float g_genr[(size_t)BATCH * F2];   // tf32-rounded relu(raw) = gen
__device__ float g_WgT [(size_t)F2 * F2];      // W_gen^T rounded, [N][K] K-major
__device__ float g_W1sT[(size_t)F3 * F3];      // round(s_k*W1[k][n])^T, [N][K]
__device__ float g_s[F3];
__device__ float g_t[F3];
__device__ float g_bias[F3];                   // t @ W1
__device__ float g_bnsum[F3];
__device__ float g_bnsq[F3];

// ------------------------------- helpers ------------------------------------
__device__ __forceinline__ float tf32r(float v) {
    uint32_t u;
    asm("cvt.rna.tf32.f32 %0, %1;" : "=r"(u) : "f"(v));
    return __uint_as_float(u);
}
__device__ __forceinline__ float4 tf32r4(float4 v) {
    return make_float4(tf32r(v.x), tf32r(v.y), tf32r(v.z), tf32r(v.w));
}
__device__ __forceinline__ uint32_t smem_u32(const void* p) {
    uint32_t a;
    asm("{ .reg .u64 t; cvta.to.shared.u64 t, %1; cvt.u32.u64 %0, t; }"
        : "=r"(a) : "l"(p));
    return a;
}
__device__ __forceinline__ void cp_async16(uint32_t dst, const void* src) {
    asm volatile("cp.async.cg.shared.global [%0], [%1], 16;" :: "r"(dst), "l"(src));
}
#define CP_COMMIT() asm volatile("cp.async.commit_group;" ::: "memory")
#define CP_WAIT(n)  asm volatile("cp.async.wait_group %0;" :: "n"(n) : "memory")

__device__ __forceinline__ void ldsm4(uint32_t& r0, uint32_t& r1, uint32_t& r2,
                                      uint32_t& r3, uint32_t addr) {
    asm volatile("ldmatrix.sync.aligned.m8n8.x4.shared.b16 {%0,%1,%2,%3}, [%4];"
                 : "=r"(r0), "=r"(r1), "=r"(r2), "=r"(r3) : "r"(addr));
}
__device__ __forceinline__ void mma_tf32(float* c, const uint32_t* a, const uint32_t* b) {
    asm volatile(
        "mma.sync.aligned.m16n8k8.row.col.f32.tf32.tf32.f32 "
        "{%0,%1,%2,%3}, {%4,%5,%6,%7}, {%8,%9}, {%0,%1,%2,%3};"
        : "+f"(c[0]), "+f"(c[1]), "+f"(c[2]), "+f"(c[3])
        : "r"(a[0]), "r"(a[1]), "r"(a[2]), "r"(a[3]), "r"(b[0]), "r"(b[1]));
}

// ---------------------------------------------------------------------------
// Gather + mean-pool (also writes tf32-rounded staging for GEMMs).
// ---------------------------------------------------------------------------
__global__ void gather_kernel(const float* __restrict__ feat,
                              const int*  __restrict__ neigh,
                              float* __restrict__ aggO)
{
    const int m = blockIdx.x;
    __shared__ int idx[DEG];
    if (threadIdx.x < DEG) idx[threadIdx.x] = neigh[(size_t)m * DEG + threadIdx.x];
    __syncthreads();

    const int c = threadIdx.x * 4;

    float4 v0 = *(const float4*)(feat + (size_t)idx[0] * FEAT + c);
    float sx = v0.x, sy = v0.y, sz = v0.z, sw = v0.w;
#pragma unroll 8
    for (int j = 1; j < DEG; j++) {
        float4 v = *(const float4*)(feat + (size_t)idx[j] * FEAT + c);
        sx += v.x; sy += v.y; sz += v.z; sw += v.w;
    }
    const float r32 = 1.0f / 32.0f;
    const float r31 = 1.0f / 31.0f;
    float4 agg = make_float4(sx * r32, sy * r32, sz * r32, sw * r32);
    float4 env = make_float4((sx - v0.x) * r31, (sy - v0.y) * r31,
                             (sz - v0.z) * r31, (sw - v0.w) * r31);

    *(float4*)(g_cat + (size_t)m * F2 + c)        = tf32r4(v0);
    *(float4*)(g_cat + (size_t)m * F2 + FEAT + c) = tf32r4(agg);
    *(float4*)(aggO  + (size_t)m * FEAT + c)      = agg;     // exact output
    *(float4*)(g_env + (size_t)m * FEAT + c)      = tf32r4(env);
}

// ---------------------------------------------------------------------------
// Transpose + tf32 round (+ optional per-source-row scale by g_s).
// ---------------------------------------------------------------------------
template <bool SCALE>
__global__ void transpose_round(const float* __restrict__ src,
                                float* __restrict__ dst, int R, int C)
{
    __shared__ float t[32][33];
    const int bx = blockIdx.x * 32, by = blockIdx.y * 32;
#pragma unroll
    for (int j = 0; j < 32; j += 8)
        t[threadIdx.y + j][threadIdx.x] =
            src[(size_t)(by + threadIdx.y + j) * C + bx + threadIdx.x];
    __syncthreads();
    const float sc = SCALE ? g_s[by + threadIdx.x] : 1.0f;
#pragma unroll
    for (int j = 0; j < 32; j += 8) {
        float v = t[threadIdx.x][threadIdx.y + j];
        if (SCALE) v *= sc;
        dst[(size_t)(bx + threadIdx.y + j) * R + by + threadIdx.x] = tf32r(v);
    }
}

// bias[n] = sum_k t[k] * W1[k][n].
__global__ void bias_kernel(const float* __restrict__ W1)
{
    const int n = blockIdx.x * 32 + (threadIdx.x & 31);
    const int kl = threadIdx.x >> 5;   // 0..7
    float sum = 0.f;
    for (int k = kl; k < F3; k += 8)
        sum += g_t[k] * W1[(size_t)k * F3 + n];
    __shared__ float red[8][32];
    red[kl][threadIdx.x & 31] = sum;
    __syncthreads();
    if (kl == 0) {
#pragma unroll
        for (int r = 1; r < 8; r++) sum += red[r][threadIdx.x & 31];
        g_bias[n] = sum;
    }
}

// ---------------------------------------------------------------------------
// tf32 mma.sync GEMM: block 128x256x32, 512 threads, 16 warps (2x8),
// warp tile 64x32. 4-stage cp.async ring, ldmatrix operand loads.
// SMEM per stage: As[128][36] + Bs[256][36], rows of 144 B.
// ---------------------------------------------------------------------------
#define BM 128
#define BN 256
#define BK 32
#define NSTAGE 4
#define NTHREADS 512
#define OP_STRIDE 144
#define A_BYTES (BM * OP_STRIDE)                   // 18432
#define B_BYTES (BN * OP_STRIDE)                   // 36864
#define STAGE_BYTES (A_BYTES + B_BYTES)            // 55296

struct GemmCore {
    uint32_t sbase;
    int tid, lane, wm, wn, lr, lc;
    uint32_t aOff, bOff;

    __device__ __forceinline__ void init(uint32_t sb) {
        sbase = sb;
        tid = threadIdx.x; lane = tid & 31;
        const int wid = tid >> 5;
        wm = wid >> 3;           // 0..1
        wn = wid & 7;            // 0..7
        lr = lane >> 2; lc = lane & 3;
        const int a_row = wm * 64 + (lane & 15);
        const int a_col = (lane >> 4) * 4;
        aOff = (uint32_t)a_row * OP_STRIDE + a_col * 4;
        const int b_row = wn * 32 + (lane & 7) + ((lane >> 4) * 8);
        const int b_col = ((lane >> 3) & 1) * 4;
        bOff = (uint32_t)b_row * OP_STRIDE + b_col * 4;
    }

    __device__ __forceinline__ void load_stage(const float* Ap, int lda,
                                               const float* Bp, int ldb, int s) {
        const uint32_t a_s = sbase + (uint32_t)s * STAGE_BYTES;
        const uint32_t b_s = a_s + A_BYTES;
#pragma unroll
        for (int u = 0; u < 2; u++) {              // A: 1024 16B chunks
            int ch = tid + u * NTHREADS;
            int row = ch >> 3, c16 = ch & 7;
            cp_async16(a_s + (uint32_t)row * OP_STRIDE + c16 * 16,
                       Ap + (size_t)row * lda + c16 * 4);
        }
#pragma unroll
        for (int u = 0; u < 4; u++) {              // B: 2048 16B chunks
            int ch = tid + u * NTHREADS;
            int row = ch >> 3, c16 = ch & 7;
            cp_async16(b_s + (uint32_t)row * OP_STRIDE + c16 * 16,
                       Bp + (size_t)row * ldb + c16 * 4);
        }
    }

    __device__ __forceinline__ void compute_stage(int s, float acc[4][4][4]) {
        const uint32_t a_s0 = sbase + (uint32_t)s * STAGE_BYTES;
#pragma unroll
        for (int k8 = 0; k8 < BK / 8; k8++) {
            const uint32_t a_s = a_s0 + (uint32_t)k8 * 32;
            const uint32_t b_s = a_s + A_BYTES;
            uint32_t a[4][4], b[2][4];
#pragma unroll
            for (int mi = 0; mi < 4; mi++)
                ldsm4(a[mi][0], a[mi][1], a[mi][2], a[mi][3],
                      a_s + aOff + (uint32_t)mi * (16 * OP_STRIDE));
#pragma unroll
            for (int nb = 0; nb < 2; nb++)
                ldsm4(b[nb][0], b[nb][1], b[nb][2], b[nb][3],
                      b_s + bOff + (uint32_t)nb * (16 * OP_STRIDE));
#pragma unroll
            for (int mi = 0; mi < 4; mi++)
#pragma unroll
                for (int nb = 0; nb < 2; nb++) {
                    mma_tf32(acc[mi][2 * nb + 0], a[mi], &b[nb][0]);
                    mma_tf32(acc[mi][2 * nb + 1], a[mi], &b[nb][2]);
                }
        }
    }
};

// GEMM1 + GEMM2 merged via blockIdx.z.
// z=0: raw/gen/genr = cat @ WgT      (K=F2)
// z=1: eraw/egen    = env @ WgT+FEAT (K=FEAT)
__global__ void __launch_bounds__(NTHREADS, 1)
mma_gemm12(const float* __restrict__ cat, const float* __restrict__ env,
           const float* __restrict__ WgT,
           float* __restrict__ raw, float* __restrict__ gen,
           float* __restrict__ genr,
           float* __restrict__ eraw, float* __restrict__ egen)
{
    extern __shared__ __align__(16) char smem[];
    GemmCore g; g.init(smem_u32(smem));
    const int m0 = blockIdx.y * BM, n0 = blockIdx.x * BN;

    const float* A; const float* Bp; int K, lda;
    float *C0, *C1, *C2;
    if (blockIdx.z == 0) {
        A = cat + (size_t)m0 * F2; K = F2; lda = F2;
        Bp = WgT + (size_t)n0 * F2;
        C0 = raw; C1 = gen; C2 = genr;
    } else {
        A = env + (size_t)m0 * FEAT; K = FEAT; lda = FEAT;
        Bp = WgT + FEAT + (size_t)n0 * F2;
        C0 = eraw; C1 = egen; C2 = nullptr;
    }
    const int T = K / BK;

    float acc[4][4][4];
#pragma unroll
    for (int i = 0; i < 4; i++)
#pragma unroll
        for (int j = 0; j < 4; j++)
#pragma unroll
            for (int r = 0; r < 4; r++) acc[i][j][r] = 0.f;

    g.load_stage(A, lda, Bp, F2, 0); CP_COMMIT();
    g.load_stage(A + BK, lda, Bp + BK, F2, 1); CP_COMMIT();
    g.load_stage(A + 2 * BK, lda, Bp + 2 * BK, F2, 2); CP_COMMIT();

    for (int i = 0; i < T; i++) {
        CP_WAIT(2);
        __syncthreads();
        g.compute_stage(i & 3, acc);
        __syncthreads();
        if (i + 3 < T) {
            g.load_stage(A + (i + 3) * BK, lda, Bp + (i + 3) * BK, F2, (i + 3) & 3);
            CP_COMMIT();
        }
    }

    // Epilogue
#pragma unroll
    for (int mi = 0; mi < 4; mi++) {
#pragma unroll
        for (int half = 0; half < 2; half++) {
            const size_t row = (size_t)m0 + g.wm * 64 + mi * 16 + g.lr + half * 8;
#pragma unroll
            for (int ni = 0; ni < 4; ni++) {
                const int col = n0 + g.wn * 32 + ni * 8 + g.lc * 2;
                float x = acc[mi][ni][half * 2 + 0];
                float y = acc[mi][ni][half * 2 + 1];
                *(float2*)(C0 + row * F2 + col) = make_float2(x, y);
                float rx = fmaxf(x, 0.f), ry = fmaxf(y, 0.f);
                *(float2*)(C1 + row * F2 + col) = make_float2(rx, ry);
                if (C2)
                    *(float2*)(C2 + row * F2 + col) = make_float2(tf32r(rx), tf32r(ry));
            }
        }
    }
}

// GEMM3: to = relu([aggR | genr] @ W1sT + bias), A split at k=FEAT.
__global__ void __launch_bounds__(NTHREADS, 1)
mma_gemm3(const float* __restrict__ aggR, const float* __restrict__ genr,
          const float* __restrict__ W1sT, float* __restrict__ C0,
          const float* __restrict__ bias)
{
    extern __shared__ __align__(16) char smem[];
    GemmCore g; g.init(smem_u32(smem));
    const int m0 = blockIdx.y * BM, n0 = blockIdx.x * BN;
    const int T = F3 / BK;

    const float* Bp = W1sT + (size_t)n0 * F3;

    auto aptr = [&](int blk) -> const float* {
        int k0 = blk * BK;
        if (k0 < FEAT) return aggR + (size_t)m0 * F2 + k0;
        return genr + (size_t)m0 * F2 + (k0 - FEAT);
    };

    float acc[4][4][4];
#pragma unroll
    for (int i = 0; i < 4; i++)
#pragma unroll
        for (int j = 0; j < 4; j++)
#pragma unroll
            for (int r = 0; r < 4; r++) acc[i][j][r] = 0.f;

    g.load_stage(aptr(0), F2, Bp, F3, 0); CP_COMMIT();
    g.load_stage(aptr(1), F2, Bp + BK, F3, 1); CP_COMMIT();
    g.load_stage(aptr(2), F2, Bp + 2 * BK, F3, 2); CP_COMMIT();

    for (int i = 0; i < T; i++) {
        CP_WAIT(2);
        __syncthreads();
        g.compute_stage(i & 3, acc);
        __syncthreads();
        if (i + 3 < T) {
            g.load_stage(aptr(i + 3), F2, Bp + (i + 3) * BK, F3, (i + 3) & 3);
            CP_COMMIT();
        }
    }

#pragma unroll
    for (int mi = 0; mi < 4; mi++) {
#pragma unroll
        for (int half = 0; half < 2; half++) {
            const size_t row = (size_t)m0 + g.wm * 64 + mi * 16 + g.lr + half * 8;
#pragma unroll
            for (int ni = 0; ni < 4; ni++) {
                const int col = n0 + g.wn * 32 + ni * 8 + g.lc * 2;
                float x = fmaxf(acc[mi][ni][half * 2 + 0] + bias[col], 0.f);
                float y = fmaxf(acc[mi][ni][half * 2 + 1] + bias[col + 1], 0.f);
                *(float2*)(C0 + row * F3 + col) = make_float2(x, y);
            }
        }
    }
}

// ---------------------------------------------------------------------------
// BN stats + finalize.
// ---------------------------------------------------------------------------
__global__ void bn_stats_kernel(const float* __restrict__ agg,
                                const float* __restrict__ gen)
{
    const int c0 = blockIdx.x * 32;
    const int cx = threadIdx.x & 31;
    const int ry = threadIdx.x >> 5;
    const int c  = c0 + cx;

    const float* base;
    int stride;
    if (c0 < FEAT) { base = agg + c;          stride = FEAT; }
    else           { base = gen + (c - FEAT); stride = F2;   }

    const int r0 = blockIdx.y * 512;
    float sum = 0.f, sq = 0.f;
#pragma unroll 8
    for (int r = r0 + ry; r < r0 + 512; r += 8) {
        float v = base[(size_t)r * stride];
        sum += v; sq += v * v;
    }
    __shared__ float ssum[8][32], ssq[8][32];
    ssum[ry][cx] = sum; ssq[ry][cx] = sq;
    __syncthreads();
    if (ry == 0) {
#pragma unroll
        for (int r = 1; r < 8; r++) { sum += ssum[r][cx]; sq += ssq[r][cx]; }
        atomicAdd(&g_bnsum[c], sum);
        atomicAdd(&g_bnsq[c], sq);
    }
}

__global__ void bn_finalize(const float* __restrict__ gamma,
                            const float* __restrict__ beta)
{
    int c = blockIdx.x * blockDim.x + threadIdx.x;
    if (c >= F3) return;
    const float inv = 1.0f / (float)BATCH;
    float mean = g_bnsum[c] * inv;
    float var  = g_bnsq[c] * inv - mean * mean;
    float s = gamma[c] * rsqrtf(var + BN_EPS);
    g_s[c] = s;
    g_t[c] = beta[c] - mean * s;
}

// ---------------------------------------------------------------------------
extern "C" void kernel_launch(void* const* d_in, const int* in_sizes, int n_in,
                              void* d_out, int out_size)
{
    const float* feat  = (const float*)d_in[0];
    const float* Wg    = (const float*)d_in[1];
    const float* W1    = (const float*)d_in[2];
    const float* gamma = (const float*)d_in[3];
    const float* beta  = (const float*)d_in[4];
    const int*   neigh = (const int*)d_in[6];

    float* out   = (float*)d_out;
    float* aggO  = out + OFF_AGG;
    float* toO   = out + OFF_TO;
    float* genO  = out + OFF_GEN;
    float* rawO  = out + OFF_RAW;
    float* egenO = out + OFF_EGEN;
    float* erawO = out + OFF_ERAW;

    float *p_cat, *p_env, *p_genr, *p_WgT, *p_W1sT, *p_sum, *p_sq, *p_bias;
    cudaGetSymbolAddress((void**)&p_cat,  g_cat);
    cudaGetSymbolAddress((void**)&p_env,  g_env);
    cudaGetSymbolAddress((void**)&p_genr, g_genr);
    cudaGetSymbolAddress((void**)&p_WgT,  g_WgT);
    cudaGetSymbolAddress((void**)&p_W1sT, g_W1sT);
    cudaGetSymbolAddress((void**)&p_sum,  g_bnsum);
    cudaGetSymbolAddress((void**)&p_sq,   g_bnsq);
    cudaGetSymbolAddress((void**)&p_bias, g_bias);

    const int smem_bytes = NSTAGE * STAGE_BYTES;   // 221184
    cudaFuncSetAttribute(mma_gemm12, cudaFuncAttributeMaxDynamicSharedMemorySize, smem_bytes);
    cudaFuncSetAttribute(mma_gemm3,  cudaFuncAttributeMaxDynamicSharedMemorySize, smem_bytes);

    // 0) W_gen -> K-major rounded; BN accumulator reset
    transpose_round<false><<<dim3(F2/32, F2/32), dim3(32, 8)>>>(Wg, p_WgT, F2, F2);
    cudaMemsetAsync(p_sum, 0, F3 * sizeof(float));
    cudaMemsetAsync(p_sq,  0, F3 * sizeof(float));

    // 1) gather + pooling (+tf32-rounded staging)
    gather_kernel<<<BATCH, 128>>>(feat, neigh, aggO);

    // 2+3) GEMM1 (z=0) + GEMM2 (z=1) in one launch
    mma_gemm12<<<dim3(F2/BN, BATCH/BM, 2), NTHREADS, smem_bytes>>>(
        p_cat, p_env, p_WgT, rawO, genO, p_genr, erawO, egenO);

    // 4) BN statistics + finalize
    bn_stats_kernel<<<dim3(F3/32, 16), 256>>>(aggO, genO);
    bn_finalize<<<F3/256, 256>>>(gamma, beta);

    // 5) fold BN into GEMM3: W1sT[n][k] = round(s_k * W1[k][n]); bias = t @ W1
    transpose_round<true><<<dim3(F3/32, F3/32), dim3(32, 8)>>>(W1, p_W1sT, F3, F3);
    bias_kernel<<<F3/32, 256>>>(W1);

    // 6) to_feats = relu([agg|gen]_r @ (sW1) + bias)
    mma_gemm3<<<dim3(F3/BN, BATCH/BM), NTHREADS, smem_bytes>>>(
        p_cat + FEAT, p_genr, p_W1sT, toO, p_bias);

    (void)in_sizes; (void)n_in; (void)out_size;
}

// round 11
// speedup vs baseline: 1.5878x; 1.1738x over previous
#include <cuda_runtime.h>
#include <cuda_bf16.h>
#include <cstdint>

// Problem constants
#define BATCH 8192
#define FEAT  512
#define DEG   32
#define F2    1024   // 2*FEAT
#define F3    1536   // 3*FEAT
#define BN_EPS 1e-5f

// Output layout (floats): agg, to_feats, gen, raw, env_gen, env_raw
#define OFF_AGG   0
#define OFF_TO    (BATCH*FEAT)
#define OFF_GEN   (OFF_TO   + BATCH*F3)
#define OFF_RAW   (OFF_GEN  + BATCH*F2)
#define OFF_EGEN  (OFF_RAW  + BATCH*F2)
#define OFF_ERAW  (OFF_EGEN + BATCH*F2)

// ---------------- scratch (__device__ globals; no allocations) --------------
__device__ float g_cat [(size_t)BATCH * F2];   // [self | agg] tf32-rounded
__device__ float g_env [(size_t)BATCH * FEAT]; // env_agg tf32-rounded
__device__ float g_genr[(size_t)BATCH * F2];   // tf32-rounded relu(raw) = gen
__device__ float g_WgT [(size_t)F2 * F2];      // W_gen^T rounded, [N][K] K-major
__device__ float g_W1sT[(size_t)F3 * F3];      // round(s_k*W1[k][n])^T, [N][K]
__device__ float g_s[F3];
__device__ float g_t[F3];
__device__ float g_bias[F3];                   // t @ W1
__device__ float g_bnsum[F3];
__device__ float g_bnsq[F3];

// ------------------------------- helpers ------------------------------------
__device__ __forceinline__ float tf32r(float v) {
    uint32_t u;
    asm("cvt.rna.tf32.f32 %0, %1;" : "=r"(u) : "f"(v));
    return __uint_as_float(u);
}
__device__ __forceinline__ float4 tf32r4(float4 v) {
    return make_float4(tf32r(v.x), tf32r(v.y), tf32r(v.z), tf32r(v.w));
}
__device__ __forceinline__ uint32_t smem_u32(const void* p) {
    uint32_t a;
    asm("{ .reg .u64 t; cvta.to.shared.u64 t, %1; cvt.u32.u64 %0, t; }"
        : "=r"(a) : "l"(p));
    return a;
}
__device__ __forceinline__ void cp_async16(uint32_t dst, const void* src) {
    asm volatile("cp.async.cg.shared.global [%0], [%1], 16;" :: "r"(dst), "l"(src));
}
#define CP_COMMIT() asm volatile("cp.async.commit_group;" ::: "memory")
#define CP_WAIT(n)  asm volatile("cp.async.wait_group %0;" :: "n"(n) : "memory")

__device__ __forceinline__ void ldsm4(uint32_t& r0, uint32_t& r1, uint32_t& r2,
                                      uint32_t& r3, uint32_t addr) {
    asm volatile("ldmatrix.sync.aligned.m8n8.x4.shared.b16 {%0,%1,%2,%3}, [%4];"
                 : "=r"(r0), "=r"(r1), "=r"(r2), "=r"(r3) : "r"(addr));
}
__device__ __forceinline__ void mma_tf32(float* c, const uint32_t* a, const uint32_t* b) {
    asm volatile(
        "mma.sync.aligned.m16n8k8.row.col.f32.tf32.tf32.f32 "
        "{%0,%1,%2,%3}, {%4,%5,%6,%7}, {%8,%9}, {%0,%1,%2,%3};"
        : "+f"(c[0]), "+f"(c[1]), "+f"(c[2]), "+f"(c[3])
        : "r"(a[0]), "r"(a[1]), "r"(a[2]), "r"(a[3]), "r"(b[0]), "r"(b[1]));
}

// ---------------------------------------------------------------------------
// Gather + mean-pool (also writes tf32-rounded staging for GEMMs).
// ---------------------------------------------------------------------------
__global__ void gather_kernel(const float* __restrict__ feat,
                              const int*  __restrict__ neigh,
                              float* __restrict__ aggO)
{
    const int m = blockIdx.x;
    __shared__ int idx[DEG];
    if (threadIdx.x < DEG) idx[threadIdx.x] = neigh[(size_t)m * DEG + threadIdx.x];
    __syncthreads();

    const int c = threadIdx.x * 4;

    float4 v0 = *(const float4*)(feat + (size_t)idx[0] * FEAT + c);
    float sx = v0.x, sy = v0.y, sz = v0.z, sw = v0.w;
#pragma unroll 8
    for (int j = 1; j < DEG; j++) {
        float4 v = *(const float4*)(feat + (size_t)idx[j] * FEAT + c);
        sx += v.x; sy += v.y; sz += v.z; sw += v.w;
    }
    const float r32 = 1.0f / 32.0f;
    const float r31 = 1.0f / 31.0f;
    float4 agg = make_float4(sx * r32, sy * r32, sz * r32, sw * r32);
    float4 env = make_float4((sx - v0.x) * r31, (sy - v0.y) * r31,
                             (sz - v0.z) * r31, (sw - v0.w) * r31);

    *(float4*)(g_cat + (size_t)m * F2 + c)        = tf32r4(v0);
    *(float4*)(g_cat + (size_t)m * F2 + FEAT + c) = tf32r4(agg);
    *(float4*)(aggO  + (size_t)m * FEAT + c)      = agg;     // exact output
    *(float4*)(g_env + (size_t)m * FEAT + c)      = tf32r4(env);
}

// ---------------------------------------------------------------------------
// Transpose + tf32 round (+ optional per-source-row scale by g_s).
// ---------------------------------------------------------------------------
template <bool SCALE>
__global__ void transpose_round(const float* __restrict__ src,
                                float* __restrict__ dst, int R, int C)
{
    __shared__ float t[32][33];
    const int bx = blockIdx.x * 32, by = blockIdx.y * 32;
#pragma unroll
    for (int j = 0; j < 32; j += 8)
        t[threadIdx.y + j][threadIdx.x] =
            src[(size_t)(by + threadIdx.y + j) * C + bx + threadIdx.x];
    __syncthreads();
    const float sc = SCALE ? g_s[by + threadIdx.x] : 1.0f;
#pragma unroll
    for (int j = 0; j < 32; j += 8) {
        float v = t[threadIdx.x][threadIdx.y + j];
        if (SCALE) v *= sc;
        dst[(size_t)(bx + threadIdx.y + j) * R + by + threadIdx.x] = tf32r(v);
    }
}

// bias[n] = sum_k t[k] * W1[k][n].
__global__ void bias_kernel(const float* __restrict__ W1)
{
    const int n = blockIdx.x * 32 + (threadIdx.x & 31);
    const int kl = threadIdx.x >> 5;   // 0..7
    float sum = 0.f;
    for (int k = kl; k < F3; k += 8)
        sum += g_t[k] * W1[(size_t)k * F3 + n];
    __shared__ float red[8][32];
    red[kl][threadIdx.x & 31] = sum;
    __syncthreads();
    if (kl == 0) {
#pragma unroll
        for (int r = 1; r < 8; r++) sum += red[r][threadIdx.x & 31];
        g_bias[n] = sum;
    }
}

// ---------------------------------------------------------------------------
// tf32 mma.sync GEMM core (R8 config): block 128x256x32, 256 thr,
// 8 warps (2x4), warp 64x64, 4-stage cp.async ring, ldmatrix loads,
// register-double-buffered fragments. cp.async issue placed after the
// first k8 MMA batch so LSU bursts overlap tensor work.
// MODE 0: C0=raw, C1=relu. MODE 2: + C2=round(relu). MODE 1: C0=relu(acc+bias).
// ---------------------------------------------------------------------------
#define BM 128
#define BN 256
#define BK 32
#define NSTAGE 4
#define OP_STRIDE 144                              // 36 floats per row
#define A_BYTES (BM * OP_STRIDE)                   // 18432
#define B_BYTES (BN * OP_STRIDE)                   // 36864
#define STAGE_BYTES (A_BYTES + B_BYTES)            // 55296

template <int MODE>
__device__ __forceinline__ void
run_gemm(char* smem,
         const float* __restrict__ A, const float* __restrict__ A2,
         const float* __restrict__ BT,
         float* __restrict__ C0, float* __restrict__ C1, float* __restrict__ C2,
         const float* __restrict__ bias,
         int K, int splitK, int lda, int lda2, int ldb, int ldc,
         int m0, int n0)
{
    const uint32_t sbase = smem_u32(smem);
    const int tid = threadIdx.x, wid = tid >> 5, lane = tid & 31;
    const int wm = wid >> 2, wn = wid & 3;       // warp grid 2 x 4
    const int lr = lane >> 2, lc = lane & 3;
    const int T = K / BK;

    const float* Bp = BT + (size_t)n0 * ldb;

    auto load_stage = [&](int blk, int s) {
        const uint32_t a_s = sbase + (uint32_t)s * STAGE_BYTES;
        const uint32_t b_s = a_s + A_BYTES;
        const int k0 = blk * BK;
        const float* Ap;
        int ld;
        if (k0 < splitK) { Ap = A + (size_t)m0 * lda + k0;             ld = lda;  }
        else             { Ap = A2 + (size_t)m0 * lda2 + (k0 - splitK); ld = lda2; }
#pragma unroll
        for (int u = 0; u < 4; u++) {            // A: 1024 16B chunks
            int ch = tid + u * 256;
            int row = ch >> 3, c16 = ch & 7;
            cp_async16(a_s + (uint32_t)row * OP_STRIDE + c16 * 16,
                       Ap + (size_t)row * ld + c16 * 4);
        }
#pragma unroll
        for (int u = 0; u < 8; u++) {            // B: 2048 16B chunks
            int ch = tid + u * 256;
            int row = ch >> 3, c16 = ch & 7;
            cp_async16(b_s + (uint32_t)row * OP_STRIDE + c16 * 16,
                       Bp + (size_t)row * ldb + k0 + c16 * 4);
        }
    };

    // ldmatrix per-lane base offsets
    const int a_row = wm * 64 + (lane & 15);
    const int a_col = (lane >> 4) * 4;
    const uint32_t aOff = (uint32_t)a_row * OP_STRIDE + a_col * 4;
    const int b_row = wn * 64 + (lane & 7) + (lane >> 4) * 8;
    const int b_col = ((lane >> 3) & 1) * 4;
    const uint32_t bOff = (uint32_t)b_row * OP_STRIDE + b_col * 4;

    auto load_frags = [&](int s, int k8, uint32_t a[4][4], uint32_t b[4][4]) {
        const uint32_t a_s = sbase + (uint32_t)s * STAGE_BYTES + (uint32_t)k8 * 32;
        const uint32_t b_s = a_s + A_BYTES;
#pragma unroll
        for (int mi = 0; mi < 4; mi++)
            ldsm4(a[mi][0], a[mi][1], a[mi][2], a[mi][3],
                  a_s + aOff + (uint32_t)mi * (16 * OP_STRIDE));
#pragma unroll
        for (int nb = 0; nb < 4; nb++)
            ldsm4(b[nb][0], b[nb][1], b[nb][2], b[nb][3],
                  b_s + bOff + (uint32_t)nb * (16 * OP_STRIDE));
    };

    float acc[4][8][4];
#pragma unroll
    for (int i = 0; i < 4; i++)
#pragma unroll
        for (int j = 0; j < 8; j++)
#pragma unroll
            for (int r = 0; r < 4; r++) acc[i][j][r] = 0.f;

    load_stage(0, 0); CP_COMMIT();
    load_stage(1, 1); CP_COMMIT();
    load_stage(2, 2); CP_COMMIT();

    CP_WAIT(2);               // stage 0 complete
    __syncthreads();

    uint32_t a_cur[4][4], b_cur[4][4], a_nxt[4][4], b_nxt[4][4];
    load_frags(0, 0, a_cur, b_cur);

    for (int i = 0; i < T; i++) {
        CP_WAIT(1);
        __syncthreads();      // stages <= i+1 complete & visible

#pragma unroll
        for (int k8 = 0; k8 < BK / 8; k8++) {
            if (k8 < 3)           load_frags(i & 3, k8 + 1, a_nxt, b_nxt);
            else if (i + 1 < T)   load_frags((i + 1) & 3, 0, a_nxt, b_nxt);
#pragma unroll
            for (int mi = 0; mi < 4; mi++)
#pragma unroll
                for (int nb = 0; nb < 4; nb++) {
                    mma_tf32(acc[mi][2 * nb + 0], a_cur[mi], &b_cur[nb][0]);
                    mma_tf32(acc[mi][2 * nb + 1], a_cur[mi], &b_cur[nb][2]);
                }
            if (k8 == 0) {    // issue next stage AFTER first MMA batch
                if (i + 3 < T) load_stage(i + 3, (i + 3) & 3);
                CP_COMMIT();
            }
#pragma unroll
            for (int mi = 0; mi < 4; mi++)
#pragma unroll
                for (int r = 0; r < 4; r++) a_cur[mi][r] = a_nxt[mi][r];
#pragma unroll
            for (int nb = 0; nb < 4; nb++)
#pragma unroll
                for (int r = 0; r < 4; r++) b_cur[nb][r] = b_nxt[nb][r];
        }
    }

    // Epilogue
#pragma unroll
    for (int mi = 0; mi < 4; mi++) {
#pragma unroll
        for (int half = 0; half < 2; half++) {
            const size_t row = (size_t)m0 + wm * 64 + mi * 16 + lr + half * 8;
#pragma unroll
            for (int ni = 0; ni < 8; ni++) {
                const int col = n0 + wn * 64 + ni * 8 + lc * 2;
                float x = acc[mi][ni][half * 2 + 0];
                float y = acc[mi][ni][half * 2 + 1];
                if (MODE == 1) {
                    x = fmaxf(x + bias[col], 0.f);
                    y = fmaxf(y + bias[col + 1], 0.f);
                    *(float2*)(C0 + row * ldc + col) = make_float2(x, y);
                } else {
                    *(float2*)(C0 + row * ldc + col) = make_float2(x, y);
                    float rx = fmaxf(x, 0.f), ry = fmaxf(y, 0.f);
                    *(float2*)(C1 + row * ldc + col) = make_float2(rx, ry);
                    if (MODE == 2)
                        *(float2*)(C2 + row * ldc + col) =
                            make_float2(tf32r(rx), tf32r(ry));
                }
            }
        }
    }
}

// Merged GEMM1+GEMM2: flat grid of 512, interleaved (even bid -> GEMM1 tile,
// odd bid -> GEMM2 tile) so heavy/light tiles mix within waves.
__global__ void __launch_bounds__(256)
mma_gemm12(const float* __restrict__ cat, const float* __restrict__ env,
           const float* __restrict__ WgT,
           float* __restrict__ raw, float* __restrict__ gen,
           float* __restrict__ genr,
           float* __restrict__ eraw, float* __restrict__ egen)
{
    extern __shared__ __align__(16) char smem[];
    const int bid = blockIdx.x;
    const int z = bid & 1;
    const int t = bid >> 1;              // 0..255
    const int n0 = (t & 3) * BN;
    const int m0 = (t >> 2) * BM;

    if (z == 0) {
        run_gemm<2>(smem, cat, cat, WgT, raw, gen, genr, nullptr,
                    F2, F2, F2, F2, F2, F2, m0, n0);
    } else {
        run_gemm<0>(smem, env, env, WgT + FEAT, eraw, egen, nullptr, nullptr,
                    FEAT, FEAT, FEAT, FEAT, F2, F2, m0, n0);
    }
}

// GEMM3: to = relu([aggR | genr] @ W1sT + bias), A split at k=FEAT.
__global__ void __launch_bounds__(256)
mma_gemm3(const float* __restrict__ aggR, const float* __restrict__ genr,
          const float* __restrict__ W1sT, float* __restrict__ C0,
          const float* __restrict__ bias)
{
    extern __shared__ __align__(16) char smem[];
    const int m0 = blockIdx.y * BM, n0 = blockIdx.x * BN;
    run_gemm<1>(smem, aggR, genr, W1sT, C0, nullptr, nullptr, bias,
                F3, FEAT, F2, F2, F3, F3, m0, n0);
}

// ---------------------------------------------------------------------------
// BN stats + finalize.
// ---------------------------------------------------------------------------
__global__ void bn_stats_kernel(const float* __restrict__ agg,
                                const float* __restrict__ gen)
{
    const int c0 = blockIdx.x * 32;
    const int cx = threadIdx.x & 31;
    const int ry = threadIdx.x >> 5;
    const int c  = c0 + cx;

    const float* base;
    int stride;
    if (c0 < FEAT) { base = agg + c;          stride = FEAT; }
    else           { base = gen + (c - FEAT); stride = F2;   }

    const int r0 = blockIdx.y * 512;
    float sum = 0.f, sq = 0.f;
#pragma unroll 8
    for (int r = r0 + ry; r < r0 + 512; r += 8) {
        float v = base[(size_t)r * stride];
        sum += v; sq += v * v;
    }
    __shared__ float ssum[8][32], ssq[8][32];
    ssum[ry][cx] = sum; ssq[ry][cx] = sq;
    __syncthreads();
    if (ry == 0) {
#pragma unroll
        for (int r = 1; r < 8; r++) { sum += ssum[r][cx]; sq += ssq[r][cx]; }
        atomicAdd(&g_bnsum[c], sum);
        atomicAdd(&g_bnsq[c], sq);
    }
}

__global__ void bn_finalize(const float* __restrict__ gamma,
                            const float* __restrict__ beta)
{
    int c = blockIdx.x * blockDim.x + threadIdx.x;
    if (c >= F3) return;
    const float inv = 1.0f / (float)BATCH;
    float mean = g_bnsum[c] * inv;
    float var  = g_bnsq[c] * inv - mean * mean;
    float s = gamma[c] * rsqrtf(var + BN_EPS);
    g_s[c] = s;
    g_t[c] = beta[c] - mean * s;
}

// ---------------------------------------------------------------------------
extern "C" void kernel_launch(void* const* d_in, const int* in_sizes, int n_in,
                              void* d_out, int out_size)
{
    const float* feat  = (const float*)d_in[0];
    const float* Wg    = (const float*)d_in[1];
    const float* W1    = (const float*)d_in[2];
    const float* gamma = (const float*)d_in[3];
    const float* beta  = (const float*)d_in[4];
    const int*   neigh = (const int*)d_in[6];

    float* out   = (float*)d_out;
    float* aggO  = out + OFF_AGG;
    float* toO   = out + OFF_TO;
    float* genO  = out + OFF_GEN;
    float* rawO  = out + OFF_RAW;
    float* egenO = out + OFF_EGEN;
    float* erawO = out + OFF_ERAW;

    float *p_cat, *p_env, *p_genr, *p_WgT, *p_W1sT, *p_sum, *p_sq, *p_bias;
    cudaGetSymbolAddress((void**)&p_cat,  g_cat);
    cudaGetSymbolAddress((void**)&p_env,  g_env);
    cudaGetSymbolAddress((void**)&p_genr, g_genr);
    cudaGetSymbolAddress((void**)&p_WgT,  g_WgT);
    cudaGetSymbolAddress((void**)&p_W1sT, g_W1sT);
    cudaGetSymbolAddress((void**)&p_sum,  g_bnsum);
    cudaGetSymbolAddress((void**)&p_sq,   g_bnsq);
    cudaGetSymbolAddress((void**)&p_bias, g_bias);

    const int smem_bytes = NSTAGE * STAGE_BYTES;   // 221184
    cudaFuncSetAttribute(mma_gemm12, cudaFuncAttributeMaxDynamicSharedMemorySize, smem_bytes);
    cudaFuncSetAttribute(mma_gemm3,  cudaFuncAttributeMaxDynamicSharedMemorySize, smem_bytes);

    // 0) W_gen -> K-major rounded; BN accumulator reset
    transpose_round<false><<<dim3(F2/32, F2/32), dim3(32, 8)>>>(Wg, p_WgT, F2, F2);
    cudaMemsetAsync(p_sum, 0, F3 * sizeof(float));
    cudaMemsetAsync(p_sq,  0, F3 * sizeof(float));

    // 1) gather + pooling (+tf32-rounded staging)
    gather_kernel<<<BATCH, 128>>>(feat, neigh, aggO);

    // 2+3) GEMM1 + GEMM2 merged, interleaved flat grid
    mma_gemm12<<<512, 256, smem_bytes>>>(
        p_cat, p_env, p_WgT, rawO, genO, p_genr, erawO, egenO);

    // 4) BN statistics + finalize
    bn_stats_kernel<<<dim3(F3/32, 16), 256>>>(aggO, genO);
    bn_finalize<<<F3/256, 256>>>(gamma, beta);

    // 5) fold BN into GEMM3: W1sT[n][k] = round(s_k * W1[k][n]); bias = t @ W1
    transpose_round<true><<<dim3(F3/32, F3/32), dim3(32, 8)>>>(W1, p_W1sT, F3, F3);
    bias_kernel<<<F3/32, 256>>>(W1);

    // 6) to_feats = relu([agg|gen]_r @ (sW1) + bias)
    mma_gemm3<<<dim3(F3/BN, BATCH/BM), 256, smem_bytes>>>(
        p_cat + FEAT, p_genr, p_W1sT, toO, p_bias);

    (void)in_sizes; (void)n_in; (void)out_size;
}

// round 12
// speedup vs baseline: 1.6593x; 1.0450x over previous
#include <cuda_runtime.h>
#include <cuda_bf16.h>
#include <cstdint>

// Problem constants
#define BATCH 8192
#define FEAT  512
#define DEG   32
#define F2    1024   // 2*FEAT
#define F3    1536   // 3*FEAT
#define BN_EPS 1e-5f

// Output layout (floats): agg, to_feats, gen, raw, env_gen, env_raw
#define OFF_AGG   0
#define OFF_TO    (BATCH*FEAT)
#define OFF_GEN   (OFF_TO   + BATCH*F3)
#define OFF_RAW   (OFF_GEN  + BATCH*F2)
#define OFF_EGEN  (OFF_RAW  + BATCH*F2)
#define OFF_ERAW  (OFF_EGEN + BATCH*F2)

// ---------------- scratch (__device__ globals; no allocations) --------------
__device__ float g_cat [(size_t)BATCH * F2];   // [self | agg] tf32-rounded
__device__ float g_env [(size_t)BATCH * FEAT]; // env_agg tf32-rounded
__device__ float g_genr[(size_t)BATCH * F2];   // tf32-rounded relu(raw) = gen
__device__ float g_WgT [(size_t)F2 * F2];      // W_gen^T rounded, [N][K] K-major
__device__ float g_W1sT[(size_t)F3 * F3];      // round(s_k*W1[k][n])^T, [N][K]
__device__ float g_s[F3];
__device__ float g_t[F3];
__device__ float g_bias[F3];                   // t @ W1
__device__ float g_bnsum[F3];
__device__ float g_bnsq[F3];

// ------------------------------- helpers ------------------------------------
__device__ __forceinline__ float tf32r(float v) {
    uint32_t u;
    asm("cvt.rna.tf32.f32 %0, %1;" : "=r"(u) : "f"(v));
    return __uint_as_float(u);
}
__device__ __forceinline__ float4 tf32r4(float4 v) {
    return make_float4(tf32r(v.x), tf32r(v.y), tf32r(v.z), tf32r(v.w));
}
__device__ __forceinline__ uint32_t smem_u32(const void* p) {
    uint32_t a;
    asm("{ .reg .u64 t; cvta.to.shared.u64 t, %1; cvt.u32.u64 %0, t; }"
        : "=r"(a) : "l"(p));
    return a;
}
__device__ __forceinline__ void cp_async16(uint32_t dst, const void* src) {
    asm volatile("cp.async.cg.shared.global [%0], [%1], 16;" :: "r"(dst), "l"(src));
}
#define CP_COMMIT() asm volatile("cp.async.commit_group;" ::: "memory")
#define CP_WAIT(n)  asm volatile("cp.async.wait_group %0;" :: "n"(n) : "memory")

__device__ __forceinline__ void ldsm4(uint32_t& r0, uint32_t& r1, uint32_t& r2,
                                      uint32_t& r3, uint32_t addr) {
    asm volatile("ldmatrix.sync.aligned.m8n8.x4.shared.b16 {%0,%1,%2,%3}, [%4];"
                 : "=r"(r0), "=r"(r1), "=r"(r2), "=r"(r3) : "r"(addr));
}
__device__ __forceinline__ void mma_tf32(float* c, const uint32_t* a, const uint32_t* b) {
    asm volatile(
        "mma.sync.aligned.m16n8k8.row.col.f32.tf32.tf32.f32 "
        "{%0,%1,%2,%3}, {%4,%5,%6,%7}, {%8,%9}, {%0,%1,%2,%3};"
        : "+f"(c[0]), "+f"(c[1]), "+f"(c[2]), "+f"(c[3])
        : "r"(a[0]), "r"(a[1]), "r"(a[2]), "r"(a[3]), "r"(b[0]), "r"(b[1]));
}

// ---------------------------------------------------------------------------
// Gather + mean-pool (also writes tf32-rounded staging for GEMMs).
// ---------------------------------------------------------------------------
__global__ void gather_kernel(const float* __restrict__ feat,
                              const int*  __restrict__ neigh,
                              float* __restrict__ aggO)
{
    const int m = blockIdx.x;
    __shared__ int idx[DEG];
    if (threadIdx.x < DEG) idx[threadIdx.x] = neigh[(size_t)m * DEG + threadIdx.x];
    __syncthreads();

    const int c = threadIdx.x * 4;

    float4 v0 = *(const float4*)(feat + (size_t)idx[0] * FEAT + c);
    float sx = v0.x, sy = v0.y, sz = v0.z, sw = v0.w;
#pragma unroll 8
    for (int j = 1; j < DEG; j++) {
        float4 v = *(const float4*)(feat + (size_t)idx[j] * FEAT + c);
        sx += v.x; sy += v.y; sz += v.z; sw += v.w;
    }
    const float r32 = 1.0f / 32.0f;
    const float r31 = 1.0f / 31.0f;
    float4 agg = make_float4(sx * r32, sy * r32, sz * r32, sw * r32);
    float4 env = make_float4((sx - v0.x) * r31, (sy - v0.y) * r31,
                             (sz - v0.z) * r31, (sw - v0.w) * r31);

    *(float4*)(g_cat + (size_t)m * F2 + c)        = tf32r4(v0);
    *(float4*)(g_cat + (size_t)m * F2 + FEAT + c) = tf32r4(agg);
    *(float4*)(aggO  + (size_t)m * FEAT + c)      = agg;     // exact output
    *(float4*)(g_env + (size_t)m * FEAT + c)      = tf32r4(env);
}

// ---------------------------------------------------------------------------
// Transpose + tf32 round. SCALE variant also multiplies by g_s[k] and
// accumulates g_bias[n] += sum_k g_t[k]*W1[k][n] (atomic per 32x32 tile).
// ---------------------------------------------------------------------------
template <bool SCALE>
__global__ void transpose_round(const float* __restrict__ src,
                                float* __restrict__ dst, int R, int C)
{
    __shared__ float t[32][33];
    __shared__ float red[8][32];
    const int bx = blockIdx.x * 32, by = blockIdx.y * 32;
#pragma unroll
    for (int j = 0; j < 32; j += 8)
        t[threadIdx.y + j][threadIdx.x] =
            src[(size_t)(by + threadIdx.y + j) * C + bx + threadIdx.x];
    __syncthreads();
    const float sc = SCALE ? g_s[by + threadIdx.x] : 1.0f;
#pragma unroll
    for (int j = 0; j < 32; j += 8) {
        float v = t[threadIdx.x][threadIdx.y + j];
        if (SCALE) v *= sc;
        dst[(size_t)(bx + threadIdx.y + j) * R + by + threadIdx.x] = tf32r(v);
    }
    if (SCALE) {
        // bias partial: rows k = by..by+31 of this tile, cols n = bx..bx+31
        float part = 0.f;
#pragma unroll
        for (int i = 0; i < 4; i++) {
            int kl = threadIdx.y + i * 8;
            part += g_t[by + kl] * t[kl][threadIdx.x];
        }
        red[threadIdx.y][threadIdx.x] = part;
        __syncthreads();
        if (threadIdx.y == 0) {
            float tot = part;
#pragma unroll
            for (int r = 1; r < 8; r++) tot += red[r][threadIdx.x];
            atomicAdd(&g_bias[bx + threadIdx.x], tot);
        }
    }
}

// ---------------------------------------------------------------------------
// tf32 mma.sync GEMM core (R8 config): block 128x256x32, 256 thr,
// 8 warps (2x4), warp 64x64, 4-stage cp.async ring, ldmatrix loads,
// register-double-buffered fragments, deferred cp.async issue.
// MODE 0: C0=raw, C1=relu. MODE 2: + C2=round(relu) + fused gen BN stats.
// MODE 1: C0=relu(acc+bias).
// ---------------------------------------------------------------------------
#define BM 128
#define BN 256
#define BK 32
#define NSTAGE 4
#define OP_STRIDE 144                              // 36 floats per row
#define A_BYTES (BM * OP_STRIDE)                   // 18432
#define B_BYTES (BN * OP_STRIDE)                   // 36864
#define STAGE_BYTES (A_BYTES + B_BYTES)            // 55296

template <int MODE>
__device__ __forceinline__ void
run_gemm(char* smem,
         const float* __restrict__ A, const float* __restrict__ A2,
         const float* __restrict__ BT,
         float* __restrict__ C0, float* __restrict__ C1, float* __restrict__ C2,
         const float* __restrict__ bias,
         int K, int splitK, int lda, int lda2, int ldb, int ldc,
         int m0, int n0)
{
    const uint32_t sbase = smem_u32(smem);
    const int tid = threadIdx.x, wid = tid >> 5, lane = tid & 31;
    const int wm = wid >> 2, wn = wid & 3;       // warp grid 2 x 4
    const int lr = lane >> 2, lc = lane & 3;
    const int T = K / BK;

    const float* Bp = BT + (size_t)n0 * ldb;

    auto load_stage = [&](int blk, int s) {
        const uint32_t a_s = sbase + (uint32_t)s * STAGE_BYTES;
        const uint32_t b_s = a_s + A_BYTES;
        const int k0 = blk * BK;
        const float* Ap;
        int ld;
        if (k0 < splitK) { Ap = A + (size_t)m0 * lda + k0;             ld = lda;  }
        else             { Ap = A2 + (size_t)m0 * lda2 + (k0 - splitK); ld = lda2; }
#pragma unroll
        for (int u = 0; u < 4; u++) {            // A: 1024 16B chunks
            int ch = tid + u * 256;
            int row = ch >> 3, c16 = ch & 7;
            cp_async16(a_s + (uint32_t)row * OP_STRIDE + c16 * 16,
                       Ap + (size_t)row * ld + c16 * 4);
        }
#pragma unroll
        for (int u = 0; u < 8; u++) {            // B: 2048 16B chunks
            int ch = tid + u * 256;
            int row = ch >> 3, c16 = ch & 7;
            cp_async16(b_s + (uint32_t)row * OP_STRIDE + c16 * 16,
                       Bp + (size_t)row * ldb + k0 + c16 * 4);
        }
    };

    // ldmatrix per-lane base offsets
    const int a_row = wm * 64 + (lane & 15);
    const int a_col = (lane >> 4) * 4;
    const uint32_t aOff = (uint32_t)a_row * OP_STRIDE + a_col * 4;
    const int b_row = wn * 64 + (lane & 7) + (lane >> 4) * 8;
    const int b_col = ((lane >> 3) & 1) * 4;
    const uint32_t bOff = (uint32_t)b_row * OP_STRIDE + b_col * 4;

    auto load_frags = [&](int s, int k8, uint32_t a[4][4], uint32_t b[4][4]) {
        const uint32_t a_s = sbase + (uint32_t)s * STAGE_BYTES + (uint32_t)k8 * 32;
        const uint32_t b_s = a_s + A_BYTES;
#pragma unroll
        for (int mi = 0; mi < 4; mi++)
            ldsm4(a[mi][0], a[mi][1], a[mi][2], a[mi][3],
                  a_s + aOff + (uint32_t)mi * (16 * OP_STRIDE));
#pragma unroll
        for (int nb = 0; nb < 4; nb++)
            ldsm4(b[nb][0], b[nb][1], b[nb][2], b[nb][3],
                  b_s + bOff + (uint32_t)nb * (16 * OP_STRIDE));
    };

    float acc[4][8][4];
#pragma unroll
    for (int i = 0; i < 4; i++)
#pragma unroll
        for (int j = 0; j < 8; j++)
#pragma unroll
            for (int r = 0; r < 4; r++) acc[i][j][r] = 0.f;

    load_stage(0, 0); CP_COMMIT();
    load_stage(1, 1); CP_COMMIT();
    load_stage(2, 2); CP_COMMIT();

    CP_WAIT(2);               // stage 0 complete
    __syncthreads();

    uint32_t a_cur[4][4], b_cur[4][4], a_nxt[4][4], b_nxt[4][4];
    load_frags(0, 0, a_cur, b_cur);

    for (int i = 0; i < T; i++) {
        CP_WAIT(1);
        __syncthreads();      // stages <= i+1 complete & visible

#pragma unroll
        for (int k8 = 0; k8 < BK / 8; k8++) {
            if (k8 < 3)           load_frags(i & 3, k8 + 1, a_nxt, b_nxt);
            else if (i + 1 < T)   load_frags((i + 1) & 3, 0, a_nxt, b_nxt);
#pragma unroll
            for (int mi = 0; mi < 4; mi++)
#pragma unroll
                for (int nb = 0; nb < 4; nb++) {
                    mma_tf32(acc[mi][2 * nb + 0], a_cur[mi], &b_cur[nb][0]);
                    mma_tf32(acc[mi][2 * nb + 1], a_cur[mi], &b_cur[nb][2]);
                }
            if (k8 == 0) {    // issue next stage AFTER first MMA batch
                if (i + 3 < T) load_stage(i + 3, (i + 3) & 3);
                CP_COMMIT();
            }
#pragma unroll
            for (int mi = 0; mi < 4; mi++)
#pragma unroll
                for (int r = 0; r < 4; r++) a_cur[mi][r] = a_nxt[mi][r];
#pragma unroll
            for (int nb = 0; nb < 4; nb++)
#pragma unroll
                for (int r = 0; r < 4; r++) b_cur[nb][r] = b_nxt[nb][r];
        }
    }

    // Epilogue: stores
#pragma unroll
    for (int mi = 0; mi < 4; mi++) {
#pragma unroll
        for (int half = 0; half < 2; half++) {
            const size_t row = (size_t)m0 + wm * 64 + mi * 16 + lr + half * 8;
#pragma unroll
            for (int ni = 0; ni < 8; ni++) {
                const int col = n0 + wn * 64 + ni * 8 + lc * 2;
                float x = acc[mi][ni][half * 2 + 0];
                float y = acc[mi][ni][half * 2 + 1];
                if (MODE == 1) {
                    x = fmaxf(x + bias[col], 0.f);
                    y = fmaxf(y + bias[col + 1], 0.f);
                    *(float2*)(C0 + row * ldc + col) = make_float2(x, y);
                } else {
                    *(float2*)(C0 + row * ldc + col) = make_float2(x, y);
                    float rx = fmaxf(x, 0.f), ry = fmaxf(y, 0.f);
                    *(float2*)(C1 + row * ldc + col) = make_float2(rx, ry);
                    if (MODE == 2)
                        *(float2*)(C2 + row * ldc + col) =
                            make_float2(tf32r(rx), tf32r(ry));
                }
            }
        }
    }

    // Fused BN stats over gen = relu(acc) (MODE 2 only).
    if (MODE == 2) {
#pragma unroll
        for (int ni = 0; ni < 8; ni++) {
            float s0 = 0.f, q0 = 0.f, s1 = 0.f, q1 = 0.f;
#pragma unroll
            for (int mi = 0; mi < 4; mi++) {
#pragma unroll
                for (int half = 0; half < 2; half++) {
                    float rx = fmaxf(acc[mi][ni][half * 2 + 0], 0.f);
                    float ry = fmaxf(acc[mi][ni][half * 2 + 1], 0.f);
                    s0 += rx; q0 += rx * rx;
                    s1 += ry; q1 += ry * ry;
                }
            }
#pragma unroll
            for (int msk = 4; msk <= 16; msk <<= 1) {
                s0 += __shfl_xor_sync(0xffffffffu, s0, msk);
                q0 += __shfl_xor_sync(0xffffffffu, q0, msk);
                s1 += __shfl_xor_sync(0xffffffffu, s1, msk);
                q1 += __shfl_xor_sync(0xffffffffu, q1, msk);
            }
            if (lr == 0) {
                const int col = n0 + wn * 64 + ni * 8 + lc * 2;
                atomicAdd(&g_bnsum[FEAT + col],     s0);
                atomicAdd(&g_bnsq [FEAT + col],     q0);
                atomicAdd(&g_bnsum[FEAT + col + 1], s1);
                atomicAdd(&g_bnsq [FEAT + col + 1], q1);
            }
        }
    }
}

// Merged GEMM1+GEMM2: flat grid of 512, interleaved.
__global__ void __launch_bounds__(256)
mma_gemm12(const float* __restrict__ cat, const float* __restrict__ env,
           const float* __restrict__ WgT,
           float* __restrict__ raw, float* __restrict__ gen,
           float* __restrict__ genr,
           float* __restrict__ eraw, float* __restrict__ egen)
{
    extern __shared__ __align__(16) char smem[];
    const int bid = blockIdx.x;
    const int z = bid & 1;
    const int t = bid >> 1;              // 0..255
    const int n0 = (t & 3) * BN;
    const int m0 = (t >> 2) * BM;

    if (z == 0) {
        run_gemm<2>(smem, cat, cat, WgT, raw, gen, genr, nullptr,
                    F2, F2, F2, F2, F2, F2, m0, n0);
    } else {
        run_gemm<0>(smem, env, env, WgT + FEAT, eraw, egen, nullptr, nullptr,
                    FEAT, FEAT, FEAT, FEAT, F2, F2, m0, n0);
    }
}

// GEMM3: to = relu([aggR | genr] @ W1sT + bias), A split at k=FEAT.
__global__ void __launch_bounds__(256)
mma_gemm3(const float* __restrict__ aggR, const float* __restrict__ genr,
          const float* __restrict__ W1sT, float* __restrict__ C0,
          const float* __restrict__ bias)
{
    extern __shared__ __align__(16) char smem[];
    const int m0 = blockIdx.y * BM, n0 = blockIdx.x * BN;
    run_gemm<1>(smem, aggR, genr, W1sT, C0, nullptr, nullptr, bias,
                F3, FEAT, F2, F2, F3, F3, m0, n0);
}

// ---------------------------------------------------------------------------
// BN stats for agg columns only (0..511); gen stats come from GEMM12 epilogue.
// ---------------------------------------------------------------------------
__global__ void bn_stats_agg(const float* __restrict__ agg)
{
    const int c0 = blockIdx.x * 32;
    const int cx = threadIdx.x & 31;
    const int ry = threadIdx.x >> 5;
    const int c  = c0 + cx;

    const float* base = agg + c;

    const int r0 = blockIdx.y * 512;
    float sum = 0.f, sq = 0.f;
#pragma unroll 8
    for (int r = r0 + ry; r < r0 + 512; r += 8) {
        float v = base[(size_t)r * FEAT];
        sum += v; sq += v * v;
    }
    __shared__ float ssum[8][32], ssq[8][32];
    ssum[ry][cx] = sum; ssq[ry][cx] = sq;
    __syncthreads();
    if (ry == 0) {
#pragma unroll
        for (int r = 1; r < 8; r++) { sum += ssum[r][cx]; sq += ssq[r][cx]; }
        atomicAdd(&g_bnsum[c], sum);
        atomicAdd(&g_bnsq[c], sq);
    }
}

__global__ void bn_finalize(const float* __restrict__ gamma,
                            const float* __restrict__ beta)
{
    int c = blockIdx.x * blockDim.x + threadIdx.x;
    if (c >= F3) return;
    const float inv = 1.0f / (float)BATCH;
    float mean = g_bnsum[c] * inv;
    float var  = g_bnsq[c] * inv - mean * mean;
    float s = gamma[c] * rsqrtf(var + BN_EPS);
    g_s[c] = s;
    g_t[c] = beta[c] - mean * s;
}

// ---------------------------------------------------------------------------
extern "C" void kernel_launch(void* const* d_in, const int* in_sizes, int n_in,
                              void* d_out, int out_size)
{
    const float* feat  = (const float*)d_in[0];
    const float* Wg    = (const float*)d_in[1];
    const float* W1    = (const float*)d_in[2];
    const float* gamma = (const float*)d_in[3];
    const float* beta  = (const float*)d_in[4];
    const int*   neigh = (const int*)d_in[6];

    float* out   = (float*)d_out;
    float* aggO  = out + OFF_AGG;
    float* toO   = out + OFF_TO;
    float* genO  = out + OFF_GEN;
    float* rawO  = out + OFF_RAW;
    float* egenO = out + OFF_EGEN;
    float* erawO = out + OFF_ERAW;

    float *p_cat, *p_env, *p_genr, *p_WgT, *p_W1sT, *p_sum, *p_sq, *p_bias;
    cudaGetSymbolAddress((void**)&p_cat,  g_cat);
    cudaGetSymbolAddress((void**)&p_env,  g_env);
    cudaGetSymbolAddress((void**)&p_genr, g_genr);
    cudaGetSymbolAddress((void**)&p_WgT,  g_WgT);
    cudaGetSymbolAddress((void**)&p_W1sT, g_W1sT);
    cudaGetSymbolAddress((void**)&p_sum,  g_bnsum);
    cudaGetSymbolAddress((void**)&p_sq,   g_bnsq);
    cudaGetSymbolAddress((void**)&p_bias, g_bias);

    const int smem_bytes = NSTAGE * STAGE_BYTES;   // 221184
    cudaFuncSetAttribute(mma_gemm12, cudaFuncAttributeMaxDynamicSharedMemorySize, smem_bytes);
    cudaFuncSetAttribute(mma_gemm3,  cudaFuncAttributeMaxDynamicSharedMemorySize, smem_bytes);

    // 0) W_gen -> K-major rounded; BN/bias accumulator reset
    transpose_round<false><<<dim3(F2/32, F2/32), dim3(32, 8)>>>(Wg, p_WgT, F2, F2);
    cudaMemsetAsync(p_sum, 0, F3 * sizeof(float));
    cudaMemsetAsync(p_sq,  0, F3 * sizeof(float));
    cudaMemsetAsync(p_bias, 0, F3 * sizeof(float));

    // 1) gather + pooling (+tf32-rounded staging)
    gather_kernel<<<BATCH, 128>>>(feat, neigh, aggO);

    // 2+3) GEMM1 + GEMM2 merged, interleaved flat grid (+ fused gen BN stats)
    mma_gemm12<<<512, 256, smem_bytes>>>(
        p_cat, p_env, p_WgT, rawO, genO, p_genr, erawO, egenO);

    // 4) agg-column BN stats + finalize
    bn_stats_agg<<<dim3(FEAT/32, 16), 256>>>(aggO);
    bn_finalize<<<F3/256, 256>>>(gamma, beta);

    // 5) W1sT[n][k] = round(s_k * W1[k][n]); bias = t @ W1 (fused, atomic)
    transpose_round<true><<<dim3(F3/32, F3/32), dim3(32, 8)>>>(W1, p_W1sT, F3, F3);

    // 6) to_feats = relu([agg|gen]_r @ (sW1) + bias)
    mma_gemm3<<<dim3(F3/BN, BATCH/BM), 256, smem_bytes>>>(
        p_cat + FEAT, p_genr, p_W1sT, toO, p_bias);

    (void)in_sizes; (void)n_in; (void)out_size;
}

// round 14
// speedup vs baseline: 1.6687x; 1.0056x over previous
#include <cuda_runtime.h>
#include <cuda_bf16.h>
#include <cstdint>

// Problem constants
#define BATCH 8192
#define FEAT  512
#define DEG   32
#define F2    1024   // 2*FEAT
#define F3    1536   // 3*FEAT
#define BN_EPS 1e-5f

// Output layout (floats): agg, to_feats, gen, raw, env_gen, env_raw
#define OFF_AGG   0
#define OFF_TO    (BATCH*FEAT)
#define OFF_GEN   (OFF_TO   + BATCH*F3)
#define OFF_RAW   (OFF_GEN  + BATCH*F2)
#define OFF_EGEN  (OFF_RAW  + BATCH*F2)
#define OFF_ERAW  (OFF_EGEN + BATCH*F2)

// ---------------- scratch (__device__ globals; no allocations) --------------
__device__ float g_cat [(size_t)BATCH * F2];   // [self | agg] tf32-rounded
__device__ float g_env [(size_t)BATCH * FEAT]; // env_agg tf32-rounded
__device__ float g_genr[(size_t)BATCH * F2];   // tf32-rounded relu(raw) = gen
__device__ float g_WgT [(size_t)F2 * F2];      // W_gen^T rounded, [N][K] K-major
__device__ float g_W1T [(size_t)F3 * F3];      // W1^T exact, [N][K]
__device__ float g_W1sT[(size_t)F3 * F3];      // round(s_k*W1[k][n])^T, [N][K]
__device__ float g_s[F3];
__device__ float g_t[F3];
__device__ float g_bias[F3];                   // t @ W1
__device__ float g_bnsum[F3];
__device__ float g_bnsq[F3];

// ------------------------------- helpers ------------------------------------
__device__ __forceinline__ float tf32r(float v) {
    uint32_t u;
    asm("cvt.rna.tf32.f32 %0, %1;" : "=r"(u) : "f"(v));
    return __uint_as_float(u);
}
__device__ __forceinline__ float4 tf32r4(float4 v) {
    return make_float4(tf32r(v.x), tf32r(v.y), tf32r(v.z), tf32r(v.w));
}
__device__ __forceinline__ uint32_t smem_u32(const void* p) {
    uint32_t a;
    asm("{ .reg .u64 t; cvta.to.shared.u64 t, %1; cvt.u32.u64 %0, t; }"
        : "=r"(a) : "l"(p));
    return a;
}
__device__ __forceinline__ void cp_async16(uint32_t dst, const void* src) {
    asm volatile("cp.async.cg.shared.global [%0], [%1], 16;" :: "r"(dst), "l"(src));
}
#define CP_COMMIT() asm volatile("cp.async.commit_group;" ::: "memory")
#define CP_WAIT(n)  asm volatile("cp.async.wait_group %0;" :: "n"(n) : "memory")

__device__ __forceinline__ void ldsm4(uint32_t& r0, uint32_t& r1, uint32_t& r2,
                                      uint32_t& r3, uint32_t addr) {
    asm volatile("ldmatrix.sync.aligned.m8n8.x4.shared.b16 {%0,%1,%2,%3}, [%4];"
                 : "=r"(r0), "=r"(r1), "=r"(r2), "=r"(r3) : "r"(addr));
}
__device__ __forceinline__ void mma_tf32(float* c, const uint32_t* a, const uint32_t* b) {
    asm volatile(
        "mma.sync.aligned.m16n8k8.row.col.f32.tf32.tf32.f32 "
        "{%0,%1,%2,%3}, {%4,%5,%6,%7}, {%8,%9}, {%0,%1,%2,%3};"
        : "+f"(c[0]), "+f"(c[1]), "+f"(c[2]), "+f"(c[3])
        : "r"(a[0]), "r"(a[1]), "r"(a[2]), "r"(a[3]), "r"(b[0]), "r"(b[1]));
}

// ---------------------------------------------------------------------------
// Gather + mean-pool (also writes tf32-rounded staging for GEMMs).
// ---------------------------------------------------------------------------
__global__ void gather_kernel(const float* __restrict__ feat,
                              const int*  __restrict__ neigh,
                              float* __restrict__ aggO)
{
    const int m = blockIdx.x;
    __shared__ int idx[DEG];
    if (threadIdx.x < DEG) idx[threadIdx.x] = neigh[(size_t)m * DEG + threadIdx.x];
    __syncthreads();

    const int c = threadIdx.x * 4;

    float4 v0 = *(const float4*)(feat + (size_t)idx[0] * FEAT + c);
    float sx = v0.x, sy = v0.y, sz = v0.z, sw = v0.w;
#pragma unroll 8
    for (int j = 1; j < DEG; j++) {
        float4 v = *(const float4*)(feat + (size_t)idx[j] * FEAT + c);
        sx += v.x; sy += v.y; sz += v.z; sw += v.w;
    }
    const float r32 = 1.0f / 32.0f;
    const float r31 = 1.0f / 31.0f;
    float4 agg = make_float4(sx * r32, sy * r32, sz * r32, sw * r32);
    float4 env = make_float4((sx - v0.x) * r31, (sy - v0.y) * r31,
                             (sz - v0.z) * r31, (sw - v0.w) * r31);

    *(float4*)(g_cat + (size_t)m * F2 + c)        = tf32r4(v0);
    *(float4*)(g_cat + (size_t)m * F2 + FEAT + c) = tf32r4(agg);
    *(float4*)(aggO  + (size_t)m * FEAT + c)      = agg;     // exact output
    *(float4*)(g_env + (size_t)m * FEAT + c)      = tf32r4(env);
}

// ---------------------------------------------------------------------------
// Transpose kernels: ROUND=true applies tf32 rounding to the output.
// ---------------------------------------------------------------------------
template <bool ROUND>
__global__ void transpose_k(const float* __restrict__ src,
                            float* __restrict__ dst, int R, int C)
{
    __shared__ float t[32][33];
    const int bx = blockIdx.x * 32, by = blockIdx.y * 32;
#pragma unroll
    for (int j = 0; j < 32; j += 8)
        t[threadIdx.y + j][threadIdx.x] =
            src[(size_t)(by + threadIdx.y + j) * C + bx + threadIdx.x];
    __syncthreads();
#pragma unroll
    for (int j = 0; j < 32; j += 8) {
        float v = t[threadIdx.x][threadIdx.y + j];
        dst[(size_t)(bx + threadIdx.y + j) * R + by + threadIdx.x] =
            ROUND ? tf32r(v) : v;
    }
}

// ---------------------------------------------------------------------------
// W1sT[n][k] = round(s[k] * W1T[n][k]);  bias[n] = sum_k t[k]*W1T[n][k].
// One block per n-row; rows are contiguous (K-major). No atomics.
// ---------------------------------------------------------------------------
__global__ void w1_scale_bias(void)
{
    const int n = blockIdx.x;
    const float4* row = (const float4*)(g_W1T + (size_t)n * F3);
    float4* dst = (float4*)(g_W1sT + (size_t)n * F3);
    float part = 0.f;
    for (int k4 = threadIdx.x; k4 < F3 / 4; k4 += blockDim.x) {
        float4 v = row[k4];
        float4 s4 = *(const float4*)(g_s + k4 * 4);
        float4 t4 = *(const float4*)(g_t + k4 * 4);
        dst[k4] = tf32r4(make_float4(v.x * s4.x, v.y * s4.y,
                                     v.z * s4.z, v.w * s4.w));
        part += t4.x * v.x + t4.y * v.y + t4.z * v.z + t4.w * v.w;
    }
    __shared__ float red[256];
    red[threadIdx.x] = part;
    __syncthreads();
    for (int o = 128; o > 0; o >>= 1) {
        if (threadIdx.x < o) red[threadIdx.x] += red[threadIdx.x + o];
        __syncthreads();
    }
    if (threadIdx.x == 0) g_bias[n] = red[0];
}

// ---------------------------------------------------------------------------
// tf32 mma.sync GEMM core (R8 config): block 128x256x32, 256 thr,
// 8 warps (2x4), warp 64x64, 4-stage cp.async ring, ldmatrix loads,
// register-double-buffered fragments, deferred cp.async issue.
// MODE 0: C0=raw, C1=relu. MODE 2: + C2=round(relu) + fused gen BN stats.
// MODE 1: C0=relu(acc+bias).
// ---------------------------------------------------------------------------
#define BM 128
#define BN 256
#define BK 32
#define NSTAGE 4
#define OP_STRIDE 144                              // 36 floats per row
#define A_BYTES (BM * OP_STRIDE)                   // 18432
#define B_BYTES (BN * OP_STRIDE)                   // 36864
#define STAGE_BYTES (A_BYTES + B_BYTES)            // 55296

template <int MODE>
__device__ __forceinline__ void
run_gemm(char* smem,
         const float* __restrict__ A, const float* __restrict__ A2,
         const float* __restrict__ BT,
         float* __restrict__ C0, float* __restrict__ C1, float* __restrict__ C2,
         const float* __restrict__ bias,
         int K, int splitK, int lda, int lda2, int ldb, int ldc,
         int m0, int n0)
{
    const uint32_t sbase = smem_u32(smem);
    const int tid = threadIdx.x, wid = tid >> 5, lane = tid & 31;
    const int wm = wid >> 2, wn = wid & 3;       // warp grid 2 x 4
    const int lr = lane >> 2, lc = lane & 3;
    const int T = K / BK;

    const float* Bp = BT + (size_t)n0 * ldb;

    auto load_stage = [&](int blk, int s) {
        const uint32_t a_s = sbase + (uint32_t)s * STAGE_BYTES;
        const uint32_t b_s = a_s + A_BYTES;
        const int k0 = blk * BK;
        const float* Ap;
        int ld;
        if (k0 < splitK) { Ap = A + (size_t)m0 * lda + k0;             ld = lda;  }
        else             { Ap = A2 + (size_t)m0 * lda2 + (k0 - splitK); ld = lda2; }
#pragma unroll
        for (int u = 0; u < 4; u++) {            // A: 1024 16B chunks
            int ch = tid + u * 256;
            int row = ch >> 3, c16 = ch & 7;
            cp_async16(a_s + (uint32_t)row * OP_STRIDE + c16 * 16,
                       Ap + (size_t)row * ld + c16 * 4);
        }
#pragma unroll
        for (int u = 0; u < 8; u++) {            // B: 2048 16B chunks
            int ch = tid + u * 256;
            int row = ch >> 3, c16 = ch & 7;
            cp_async16(b_s + (uint32_t)row * OP_STRIDE + c16 * 16,
                       Bp + (size_t)row * ldb + k0 + c16 * 4);
        }
    };

    // ldmatrix per-lane base offsets
    const int a_row = wm * 64 + (lane & 15);
    const int a_col = (lane >> 4) * 4;
    const uint32_t aOff = (uint32_t)a_row * OP_STRIDE + a_col * 4;
    const int b_row = wn * 64 + (lane & 7) + (lane >> 4) * 8;
    const int b_col = ((lane >> 3) & 1) * 4;
    const uint32_t bOff = (uint32_t)b_row * OP_STRIDE + b_col * 4;

    auto load_frags = [&](int s, int k8, uint32_t a[4][4], uint32_t b[4][4]) {
        const uint32_t a_s = sbase + (uint32_t)s * STAGE_BYTES + (uint32_t)k8 * 32;
        const uint32_t b_s = a_s + A_BYTES;
#pragma unroll
        for (int mi = 0; mi < 4; mi++)
            ldsm4(a[mi][0], a[mi][1], a[mi][2], a[mi][3],
                  a_s + aOff + (uint32_t)mi * (16 * OP_STRIDE));
#pragma unroll
        for (int nb = 0; nb < 4; nb++)
            ldsm4(b[nb][0], b[nb][1], b[nb][2], b[nb][3],
                  b_s + bOff + (uint32_t)nb * (16 * OP_STRIDE));
    };

    float acc[4][8][4];
#pragma unroll
    for (int i = 0; i < 4; i++)
#pragma unroll
        for (int j = 0; j < 8; j++)
#pragma unroll
            for (int r = 0; r < 4; r++) acc[i][j][r] = 0.f;

    load_stage(0, 0); CP_COMMIT();
    load_stage(1, 1); CP_COMMIT();
    load_stage(2, 2); CP_COMMIT();

    CP_WAIT(2);               // stage 0 complete
    __syncthreads();

    uint32_t a_cur[4][4], b_cur[4][4], a_nxt[4][4], b_nxt[4][4];
    load_frags(0, 0, a_cur, b_cur);

    for (int i = 0; i < T; i++) {
        CP_WAIT(1);
        __syncthreads();      // stages <= i+1 complete & visible

#pragma unroll
        for (int k8 = 0; k8 < BK / 8; k8++) {
            if (k8 < 3)           load_frags(i & 3, k8 + 1, a_nxt, b_nxt);
            else if (i + 1 < T)   load_frags((i + 1) & 3, 0, a_nxt, b_nxt);
#pragma unroll
            for (int mi = 0; mi < 4; mi++)
#pragma unroll
                for (int nb = 0; nb < 4; nb++) {
                    mma_tf32(acc[mi][2 * nb + 0], a_cur[mi], &b_cur[nb][0]);
                    mma_tf32(acc[mi][2 * nb + 1], a_cur[mi], &b_cur[nb][2]);
                }
            if (k8 == 0) {    // issue next stage AFTER first MMA batch
                if (i + 3 < T) load_stage(i + 3, (i + 3) & 3);
                CP_COMMIT();
            }
#pragma unroll
            for (int mi = 0; mi < 4; mi++)
#pragma unroll
                for (int r = 0; r < 4; r++) a_cur[mi][r] = a_nxt[mi][r];
#pragma unroll
            for (int nb = 0; nb < 4; nb++)
#pragma unroll
                for (int r = 0; r < 4; r++) b_cur[nb][r] = b_nxt[nb][r];
        }
    }

    // Epilogue: stores
#pragma unroll
    for (int mi = 0; mi < 4; mi++) {
#pragma unroll
        for (int half = 0; half < 2; half++) {
            const size_t row = (size_t)m0 + wm * 64 + mi * 16 + lr + half * 8;
#pragma unroll
            for (int ni = 0; ni < 8; ni++) {
                const int col = n0 + wn * 64 + ni * 8 + lc * 2;
                float x = acc[mi][ni][half * 2 + 0];
                float y = acc[mi][ni][half * 2 + 1];
                if (MODE == 1) {
                    x = fmaxf(x + bias[col], 0.f);
                    y = fmaxf(y + bias[col + 1], 0.f);
                    *(float2*)(C0 + row * ldc + col) = make_float2(x, y);
                } else {
                    *(float2*)(C0 + row * ldc + col) = make_float2(x, y);
                    float rx = fmaxf(x, 0.f), ry = fmaxf(y, 0.f);
                    *(float2*)(C1 + row * ldc + col) = make_float2(rx, ry);
                    if (MODE == 2)
                        *(float2*)(C2 + row * ldc + col) =
                            make_float2(tf32r(rx), tf32r(ry));
                }
            }
        }
    }

    // Fused BN stats over gen = relu(acc) (MODE 2 only).
    if (MODE == 2) {
#pragma unroll
        for (int ni = 0; ni < 8; ni++) {
            float s0 = 0.f, q0 = 0.f, s1 = 0.f, q1 = 0.f;
#pragma unroll
            for (int mi = 0; mi < 4; mi++) {
#pragma unroll
                for (int half = 0; half < 2; half++) {
                    float rx = fmaxf(acc[mi][ni][half * 2 + 0], 0.f);
                    float ry = fmaxf(acc[mi][ni][half * 2 + 1], 0.f);
                    s0 += rx; q0 += rx * rx;
                    s1 += ry; q1 += ry * ry;
                }
            }
#pragma unroll
            for (int msk = 4; msk <= 16; msk <<= 1) {
                s0 += __shfl_xor_sync(0xffffffffu, s0, msk);
                q0 += __shfl_xor_sync(0xffffffffu, q0, msk);
                s1 += __shfl_xor_sync(0xffffffffu, s1, msk);
                q1 += __shfl_xor_sync(0xffffffffu, q1, msk);
            }
            if (lr == 0) {
                const int col = n0 + wn * 64 + ni * 8 + lc * 2;
                atomicAdd(&g_bnsum[FEAT + col],     s0);
                atomicAdd(&g_bnsq [FEAT + col],     q0);
                atomicAdd(&g_bnsum[FEAT + col + 1], s1);
                atomicAdd(&g_bnsq [FEAT + col + 1], q1);
            }
        }
    }
}

// Merged GEMM1+GEMM2: flat grid of 512, interleaved.
__global__ void __launch_bounds__(256)
mma_gemm12(const float* __restrict__ cat, const float* __restrict__ env,
           const float* __restrict__ WgT,
           float* __restrict__ raw, float* __restrict__ gen,
           float* __restrict__ genr,
           float* __restrict__ eraw, float* __restrict__ egen)
{
    extern __shared__ __align__(16) char smem[];
    const int bid = blockIdx.x;
    const int z = bid & 1;
    const int t = bid >> 1;              // 0..255
    const int n0 = (t & 3) * BN;
    const int m0 = (t >> 2) * BM;

    if (z == 0) {
        run_gemm<2>(smem, cat, cat, WgT, raw, gen, genr, nullptr,
                    F2, F2, F2, F2, F2, F2, m0, n0);
    } else {
        run_gemm<0>(smem, env, env, WgT + FEAT, eraw, egen, nullptr, nullptr,
                    FEAT, FEAT, FEAT, FEAT, F2, F2, m0, n0);
    }
}

// GEMM3: to = relu([aggR | genr] @ W1sT + bias), A split at k=FEAT.
__global__ void __launch_bounds__(256)
mma_gemm3(const float* __restrict__ aggR, const float* __restrict__ genr,
          const float* __restrict__ W1sT, float* __restrict__ C0,
          const float* __restrict__ bias)
{
    extern __shared__ __align__(16) char smem[];
    const int m0 = blockIdx.y * BM, n0 = blockIdx.x * BN;
    run_gemm<1>(smem, aggR, genr, W1sT, C0, nullptr, nullptr, bias,
                F3, FEAT, F2, F2, F3, F3, m0, n0);
}

// ---------------------------------------------------------------------------
// BN stats for agg columns only (0..511); gen stats come from GEMM12 epilogue.
// ---------------------------------------------------------------------------
__global__ void bn_stats_agg(const float* __restrict__ agg)
{
    const int c0 = blockIdx.x * 32;
    const int cx = threadIdx.x & 31;
    const int ry = threadIdx.x >> 5;
    const int c  = c0 + cx;

    const float* base = agg + c;

    const int r0 = blockIdx.y * 512;
    float sum = 0.f, sq = 0.f;
#pragma unroll 8
    for (int r = r0 + ry; r < r0 + 512; r += 8) {
        float v = base[(size_t)r * FEAT];
        sum += v; sq += v * v;
    }
    __shared__ float ssum[8][32], ssq[8][32];
    ssum[ry][cx] = sum; ssq[ry][cx] = sq;
    __syncthreads();
    if (ry == 0) {
#pragma unroll
        for (int r = 1; r < 8; r++) { sum += ssum[r][cx]; sq += ssq[r][cx]; }
        atomicAdd(&g_bnsum[c], sum);
        atomicAdd(&g_bnsq[c], sq);
    }
}

__global__ void bn_finalize(const float* __restrict__ gamma,
                            const float* __restrict__ beta)
{
    int c = blockIdx.x * blockDim.x + threadIdx.x;
    if (c >= F3) return;
    const float inv = 1.0f / (float)BATCH;
    float mean = g_bnsum[c] * inv;
    float var  = g_bnsq[c] * inv - mean * mean;
    float s = gamma[c] * rsqrtf(var + BN_EPS);
    g_s[c] = s;
    g_t[c] = beta[c] - mean * s;
}

// ---------------------------------------------------------------------------
extern "C" void kernel_launch(void* const* d_in, const int* in_sizes, int n_in,
                              void* d_out, int out_size)
{
    const float* feat  = (const float*)d_in[0];
    const float* Wg    = (const float*)d_in[1];
    const float* W1    = (const float*)d_in[2];
    const float* gamma = (const float*)d_in[3];
    const float* beta  = (const float*)d_in[4];
    const int*   neigh = (const int*)d_in[6];

    float* out   = (float*)d_out;
    float* aggO  = out + OFF_AGG;
    float* toO   = out + OFF_TO;
    float* genO  = out + OFF_GEN;
    float* rawO  = out + OFF_RAW;
    float* egenO = out + OFF_EGEN;
    float* erawO = out + OFF_ERAW;

    float *p_cat, *p_env, *p_genr, *p_WgT, *p_W1T, *p_W1sT, *p_sum, *p_sq, *p_bias;
    cudaGetSymbolAddress((void**)&p_cat,  g_cat);
    cudaGetSymbolAddress((void**)&p_env,  g_env);
    cudaGetSymbolAddress((void**)&p_genr, g_genr);
    cudaGetSymbolAddress((void**)&p_WgT,  g_WgT);
    cudaGetSymbolAddress((void**)&p_W1T,  g_W1T);
    cudaGetSymbolAddress((void**)&p_W1sT, g_W1sT);
    cudaGetSymbolAddress((void**)&p_sum,  g_bnsum);
    cudaGetSymbolAddress((void**)&p_sq,   g_bnsq);
    cudaGetSymbolAddress((void**)&p_bias, g_bias);

    const int smem_bytes = NSTAGE * STAGE_BYTES;   // 221184
    cudaFuncSetAttribute(mma_gemm12, cudaFuncAttributeMaxDynamicSharedMemorySize, smem_bytes);
    cudaFuncSetAttribute(mma_gemm3,  cudaFuncAttributeMaxDynamicSharedMemorySize, smem_bytes);

    // Side stream + fork/join events (created fresh each call; graph-capture
    // fork via event record/wait on the capturing default stream).
    cudaStream_t s2;
    cudaStreamCreateWithFlags(&s2, cudaStreamNonBlocking);
    cudaEvent_t eFork, eW, eG, eS;
    cudaEventCreateWithFlags(&eFork, cudaEventDisableTiming);
    cudaEventCreateWithFlags(&eW,    cudaEventDisableTiming);
    cudaEventCreateWithFlags(&eG,    cudaEventDisableTiming);
    cudaEventCreateWithFlags(&eS,    cudaEventDisableTiming);

    // Fork s2 off the (capturing) default stream.
    cudaEventRecord(eFork, 0);
    cudaStreamWaitEvent(s2, eFork, 0);

    // s2 branch: weight prep + stat memsets (independent of gather).
    transpose_k<true ><<<dim3(F2/32, F2/32), dim3(32, 8), 0, s2>>>(Wg, p_WgT, F2, F2);
    transpose_k<false><<<dim3(F3/32, F3/32), dim3(32, 8), 0, s2>>>(W1, p_W1T, F3, F3);
    cudaMemsetAsync(p_sum, 0, F3 * sizeof(float), s2);
    cudaMemsetAsync(p_sq,  0, F3 * sizeof(float), s2);
    cudaEventRecord(eW, s2);

    // Main stream: gather.
    gather_kernel<<<BATCH, 128>>>(feat, neigh, aggO);
    cudaEventRecord(eG, 0);

    // s2: agg BN stats (needs gather + memsets) — overlaps GEMM12.
    cudaStreamWaitEvent(s2, eG, 0);
    bn_stats_agg<<<dim3(FEAT/32, 16), 256, 0, s2>>>(aggO);
    cudaEventRecord(eS, s2);

    // Main: GEMM1+GEMM2 (needs WgT + memsets from s2).
    cudaStreamWaitEvent(0, eW, 0);
    mma_gemm12<<<512, 256, smem_bytes>>>(
        p_cat, p_env, p_WgT, rawO, genO, p_genr, erawO, egenO);

    // Join stats branch; finalize BN, build scaled W1 + bias, GEMM3.
    cudaStreamWaitEvent(0, eS, 0);
    bn_finalize<<<F3/256, 256>>>(gamma, beta);
    w1_scale_bias<<<F3, 256>>>();
    mma_gemm3<<<dim3(F3/BN, BATCH/BM), 256, smem_bytes>>>(
        p_cat + FEAT, p_genr, p_W1sT, toO, p_bias);

    (void)in_sizes; (void)n_in; (void)out_size;
}